// round 3
// baseline (speedup 1.0000x reference)
#include <cuda_runtime.h>
#include <math.h>
#include <stdint.h>

// GPT-2 small config
#define BATCH 4
#define TLEN  1024
#define EMB   768
#define NLAYER 12
#define VOCAB 50257
#define NHEAD 12
#define HEADD 64
#define MROW  (BATCH * TLEN)   // 4096

// ---------------- scratch (device globals; no allocation allowed) ----------------
__device__ float g_x[MROW * EMB];        // residual stream
__device__ float g_h[MROW * EMB];        // layernorm output
__device__ float g_qkv[MROW * 3 * EMB];  // qkv projection
__device__ float g_y[MROW * EMB];        // attention output
__device__ float g_fc1[MROW * 4 * EMB];  // mlp hidden

// ---------------- helpers ----------------
__device__ __forceinline__ float gelu_f(float x) {
    return 0.5f * x * (1.0f + erff(x * 0.7071067811865476f));
}

// ---------------- embedding: x = wte[idx] + wpe[t] ----------------
__global__ void embed_kernel(const int* __restrict__ idx,
                             const float* __restrict__ wte,
                             const float* __restrict__ wpe,
                             float* __restrict__ x) {
    int i = blockIdx.x * blockDim.x + threadIdx.x;
    if (i >= MROW * EMB) return;
    int row = i / EMB;
    int e = i - row * EMB;
    int t = row % TLEN;
    x[i] = wte[(size_t)idx[row] * EMB + e] + wpe[(size_t)t * EMB + e];
}

// ---------------- layernorm: one block (256 thr) per row of 768 ----------------
__global__ void __launch_bounds__(256) ln_kernel(const float* __restrict__ x,
                                                 const float* __restrict__ w,
                                                 const float* __restrict__ b,
                                                 float* __restrict__ out) {
    __shared__ float red[8];
    __shared__ float s_mean, s_var;
    int row = blockIdx.x;
    int tid = threadIdx.x;
    int warp = tid >> 5, lane = tid & 31;
    const float* xr = x + (size_t)row * EMB;

    float v0 = xr[tid], v1 = xr[tid + 256], v2 = xr[tid + 512];
    float s = v0 + v1 + v2;
#pragma unroll
    for (int o = 16; o; o >>= 1) s += __shfl_xor_sync(0xffffffffu, s, o);
    if (lane == 0) red[warp] = s;
    __syncthreads();
    if (tid == 0) {
        float t = 0.f;
#pragma unroll
        for (int i = 0; i < 8; i++) t += red[i];
        s_mean = t * (1.0f / EMB);
    }
    __syncthreads();
    float m = s_mean;
    float d0 = v0 - m, d1 = v1 - m, d2 = v2 - m;
    float q = d0 * d0 + d1 * d1 + d2 * d2;
#pragma unroll
    for (int o = 16; o; o >>= 1) q += __shfl_xor_sync(0xffffffffu, q, o);
    if (lane == 0) red[warp] = q;
    __syncthreads();
    if (tid == 0) {
        float t = 0.f;
#pragma unroll
        for (int i = 0; i < 8; i++) t += red[i];
        s_var = t * (1.0f / EMB);
    }
    __syncthreads();
    float r = rsqrtf(s_var + 1e-5f);
    float* orow = out + (size_t)row * EMB;
    orow[tid]       = d0 * r * w[tid]       + b[tid];
    orow[tid + 256] = d1 * r * w[tid + 256] + b[tid + 256];
    orow[tid + 512] = d2 * r * w[tid + 512] + b[tid + 512];
}

// ---------------- tiled SGEMM: C[M,N] = A[M,K] @ B + epilogue ----------------
// EPI: 0 = none, 1 = +bias, 2 = +bias+residual, 3 = +bias then GELU
// BT:  0 = B is [K,N] row-major; 1 = B is [N,K] row-major (used transposed)
template <int EPI, int BT>
__global__ void __launch_bounds__(256) gemm_kernel(const float* __restrict__ A,
                                                   const float* __restrict__ B,
                                                   const float* __restrict__ bias,
                                                   const float* __restrict__ R,
                                                   float* __restrict__ C,
                                                   int M, int N, int K) {
    __shared__ __align__(16) float As[16][128];
    __shared__ __align__(16) float Bs[16][132];  // padded for BT store pattern

    int tid = threadIdx.x;
    int m0 = blockIdx.y * 128;
    int n0 = blockIdx.x * 128;
    int tm = tid >> 4;   // 0..15
    int tn = tid & 15;   // 0..15

    float acc[8][8];
#pragma unroll
    for (int i = 0; i < 8; i++)
#pragma unroll
        for (int j = 0; j < 8; j++) acc[i][j] = 0.f;

    for (int k0 = 0; k0 < K; k0 += 16) {
        // --- load A tile (128x16), vectorized; M and K are always multiples ---
#pragma unroll
        for (int u = 0; u < 2; u++) {
            int f = tid * 2 + u;            // 0..511 float4 slots
            int row = f >> 2;               // 0..127
            int kc = (f & 3) * 4;           // 0,4,8,12
            float4 v = *(const float4*)&A[(size_t)(m0 + row) * K + k0 + kc];
            As[kc + 0][row] = v.x;
            As[kc + 1][row] = v.y;
            As[kc + 2][row] = v.z;
            As[kc + 3][row] = v.w;
        }
        // --- load B tile (16x128) ---
        if (BT) {
            // B[n, k] layout: vectorized along k (contiguous), scatter into Bs
            int col = tid >> 1;             // 0..127
            int half = tid & 1;             // which 8 of the 16 k's
            int n = n0 + col;
            float4 u0, u1;
            if (n < N) {
                const float* bp = &B[(size_t)n * K + k0 + half * 8];
                u0 = *(const float4*)bp;
                u1 = *(const float4*)(bp + 4);
            } else {
                u0 = make_float4(0.f, 0.f, 0.f, 0.f);
                u1 = u0;
            }
            int kb = half * 8;
            Bs[kb + 0][col] = u0.x; Bs[kb + 1][col] = u0.y;
            Bs[kb + 2][col] = u0.z; Bs[kb + 3][col] = u0.w;
            Bs[kb + 4][col] = u1.x; Bs[kb + 5][col] = u1.y;
            Bs[kb + 6][col] = u1.z; Bs[kb + 7][col] = u1.w;
        } else {
            // B[k, n] layout: coalesced scalar loads with column guard
#pragma unroll
            for (int u = 0; u < 8; u++) {
                int i = tid + u * 256;      // 0..2047
                int kr = i >> 7;            // 0..15
                int nc = i & 127;           // 0..127
                int n = n0 + nc;
                Bs[kr][nc] = (n < N) ? B[(size_t)(k0 + kr) * N + n] : 0.f;
            }
        }
        __syncthreads();

#pragma unroll
        for (int k = 0; k < 16; k++) {
            float4 a0 = *(const float4*)&As[k][tm * 8];
            float4 a1 = *(const float4*)&As[k][tm * 8 + 4];
            float4 b0 = *(const float4*)&Bs[k][tn * 8];
            float4 b1 = *(const float4*)&Bs[k][tn * 8 + 4];
            float ra[8] = {a0.x, a0.y, a0.z, a0.w, a1.x, a1.y, a1.z, a1.w};
            float rb[8] = {b0.x, b0.y, b0.z, b0.w, b1.x, b1.y, b1.z, b1.w};
#pragma unroll
            for (int i = 0; i < 8; i++)
#pragma unroll
                for (int j = 0; j < 8; j++)
                    acc[i][j] = fmaf(ra[i], rb[j], acc[i][j]);
        }
        __syncthreads();
    }

    // --- epilogue ---
#pragma unroll
    for (int i = 0; i < 8; i++) {
        size_t row = (size_t)(m0 + tm * 8 + i);
#pragma unroll
        for (int j = 0; j < 8; j++) {
            int n = n0 + tn * 8 + j;
            if (n < N) {
                float c = acc[i][j];
                if (EPI >= 1) c += bias[n];
                if (EPI == 2) c += R[row * (size_t)N + n];
                if (EPI == 3) c = gelu_f(c);
                C[row * (size_t)N + n] = c;
            }
        }
    }
}

// ---------------- attention: warp-per-query online softmax ----------------
// grid: (BATCH*NHEAD, TLEN/8), block: 256 (8 warps -> 8 queries)
__global__ void __launch_bounds__(256) attn_kernel(const float* __restrict__ qkv,
                                                   float* __restrict__ y) {
    __shared__ float Ks[64][64];
    __shared__ float Vs[64][64];
    int bh = blockIdx.x;
    int b = bh / NHEAD, h = bh % NHEAD;
    int q0 = blockIdx.y * 8;
    int warp = threadIdx.x >> 5, lane = threadIdx.x & 31;
    int q = q0 + warp;

    size_t qbase = ((size_t)(b * TLEN + q)) * (3 * EMB) + h * HEADD;
    float2 qv = *(const float2*)&qkv[qbase + 2 * lane];

    float m = -1e30f, lsum = 0.f, ax = 0.f, ay = 0.f;
    int nch = q0 / 64 + 1;  // q0..q0+7 live in the same 64-key chunk

    for (int c = 0; c < nch; c++) {
        int kb = c * 64;
        for (int i = threadIdx.x; i < 64 * 64; i += 256) {
            int kk = i >> 6, d = i & 63;
            size_t base = ((size_t)(b * TLEN + kb + kk)) * (3 * EMB) + h * HEADD + d;
            Ks[kk][d] = qkv[base + EMB];
            Vs[kk][d] = qkv[base + 2 * EMB];
        }
        __syncthreads();

        int jmax = q - kb;
        if (jmax > 63) jmax = 63;
        for (int j = 0; j <= jmax; j++) {
            float s = qv.x * Ks[j][2 * lane] + qv.y * Ks[j][2 * lane + 1];
#pragma unroll
            for (int o = 16; o; o >>= 1) s += __shfl_xor_sync(0xffffffffu, s, o);
            s *= 0.125f;  // 1/sqrt(64)
            float mn = fmaxf(m, s);
            float corr = __expf(m - mn);
            float p = __expf(s - mn);
            ax = ax * corr + p * Vs[j][2 * lane];
            ay = ay * corr + p * Vs[j][2 * lane + 1];
            lsum = lsum * corr + p;
            m = mn;
        }
        __syncthreads();
    }

    float inv = 1.0f / lsum;
    float2 o2 = make_float2(ax * inv, ay * inv);
    *(float2*)&y[((size_t)(b * TLEN + q)) * EMB + h * HEADD + 2 * lane] = o2;
}

// ---------------- host launch ----------------
extern "C" void kernel_launch(void* const* d_in, const int* in_sizes, int n_in,
                              void* d_out, int out_size) {
    (void)in_sizes; (void)n_in; (void)out_size;
    const int*   x_idx  = (const int*)d_in[0];
    const float* wte    = (const float*)d_in[1];
    const float* wpe    = (const float*)d_in[2];
    const float* ln1_w  = (const float*)d_in[3];
    const float* ln1_b  = (const float*)d_in[4];
    const float* attn_w = (const float*)d_in[5];
    const float* attn_b = (const float*)d_in[6];
    const float* proj_w = (const float*)d_in[7];
    const float* proj_b = (const float*)d_in[8];
    const float* ln2_w  = (const float*)d_in[9];
    const float* ln2_b  = (const float*)d_in[10];
    const float* fc1_w  = (const float*)d_in[11];
    const float* fc1_b  = (const float*)d_in[12];
    const float* fc2_w  = (const float*)d_in[13];
    const float* fc2_b  = (const float*)d_in[14];
    const float* lnf_w  = (const float*)d_in[15];
    const float* lnf_b  = (const float*)d_in[16];
    float* out = (float*)d_out;

    float *gx, *gh, *gqkv, *gy, *gfc1;
    cudaGetSymbolAddress((void**)&gx,   g_x);
    cudaGetSymbolAddress((void**)&gh,   g_h);
    cudaGetSymbolAddress((void**)&gqkv, g_qkv);
    cudaGetSymbolAddress((void**)&gy,   g_y);
    cudaGetSymbolAddress((void**)&gfc1, g_fc1);

    embed_kernel<<<(MROW * EMB + 255) / 256, 256>>>(x_idx, wte, wpe, gx);

    for (int l = 0; l < NLAYER; l++) {
        // h = ln1(x)
        ln_kernel<<<MROW, 256>>>(gx, ln1_w + (size_t)l * EMB, ln1_b + (size_t)l * EMB, gh);
        // qkv = h @ attn_w + attn_b
        gemm_kernel<1, 0><<<dim3(3 * EMB / 128, MROW / 128), 256>>>(
            gh, attn_w + (size_t)l * EMB * 3 * EMB, attn_b + (size_t)l * 3 * EMB,
            nullptr, gqkv, MROW, 3 * EMB, EMB);
        // y = attention(qkv)
        attn_kernel<<<dim3(BATCH * NHEAD, TLEN / 8), 256>>>(gqkv, gy);
        // x = x + y @ proj_w + proj_b
        gemm_kernel<2, 0><<<dim3(EMB / 128, MROW / 128), 256>>>(
            gy, proj_w + (size_t)l * EMB * EMB, proj_b + (size_t)l * EMB,
            gx, gx, MROW, EMB, EMB);
        // h = ln2(x)
        ln_kernel<<<MROW, 256>>>(gx, ln2_w + (size_t)l * EMB, ln2_b + (size_t)l * EMB, gh);
        // fc1 = gelu(h @ fc1_w + fc1_b)
        gemm_kernel<3, 0><<<dim3(4 * EMB / 128, MROW / 128), 256>>>(
            gh, fc1_w + (size_t)l * EMB * 4 * EMB, fc1_b + (size_t)l * 4 * EMB,
            nullptr, gfc1, MROW, 4 * EMB, EMB);
        // x = x + fc1 @ fc2_w + fc2_b
        gemm_kernel<2, 0><<<dim3(EMB / 128, MROW / 128), 256>>>(
            gfc1, fc2_w + (size_t)l * 4 * EMB * EMB, fc2_b + (size_t)l * EMB,
            gx, gx, MROW, EMB, 4 * EMB);
    }

    // h = lnf(x)
    ln_kernel<<<MROW, 256>>>(gx, lnf_w, lnf_b, gh);
    // logits = h @ wte^T   (B accessed transposed)
    gemm_kernel<0, 1><<<dim3((VOCAB + 127) / 128, MROW / 128), 256>>>(
        gh, wte, nullptr, nullptr, out, MROW, VOCAB, EMB);
}

// round 8
// speedup vs baseline: 1.8411x; 1.8411x over previous
#include <cuda_runtime.h>
#include <cuda_bf16.h>
#include <math.h>
#include <stdint.h>

// GPT-2 small config
#define BATCH 4
#define TLEN  1024
#define EMB   768
#define NLAYER 12
#define VOCAB 50257
#define NHEAD 12
#define HEADD 64
#define MROW  (BATCH * TLEN)   // 4096

// ---------------- scratch (device globals; no allocation allowed) ----------------
__device__ float g_x[MROW * EMB];        // residual stream
__device__ float g_h[MROW * EMB];        // layernorm output
__device__ float g_qkv[MROW * 3 * EMB];  // qkv projection
__device__ float g_y[MROW * EMB];        // attention output
__device__ float g_fc1[MROW * 4 * EMB];  // mlp hidden

// ======================= helpers =======================
__device__ __forceinline__ uint32_t smem_u32(const void* p) {
    uint32_t a;
    asm("{ .reg .u64 t; cvta.to.shared.u64 t, %1; cvt.u32.u64 %0, t; }"
        : "=r"(a) : "l"(p));
    return a;
}

__device__ __forceinline__ uint32_t packbf2(float a, float b) {
    __nv_bfloat162 t = __floats2bfloat162_rn(a, b);
    return reinterpret_cast<uint32_t&>(t);
}
__device__ __forceinline__ float bfh(float a) {
    return __bfloat162float(__float2bfloat16_rn(a));
}
__device__ __forceinline__ void sts64(uint32_t addr, uint32_t w0, uint32_t w1) {
    asm volatile("st.shared.v2.b32 [%0], {%1, %2};" :: "r"(addr), "r"(w0), "r"(w1) : "memory");
}
__device__ __forceinline__ void ldsm_x4(uint32_t addr, uint32_t* r) {
    asm volatile("ldmatrix.sync.aligned.m8n8.x4.shared.b16 {%0,%1,%2,%3}, [%4];"
                 : "=r"(r[0]), "=r"(r[1]), "=r"(r[2]), "=r"(r[3]) : "r"(addr));
}
__device__ __forceinline__ void ldsm_x2(uint32_t addr, uint32_t* r) {
    asm volatile("ldmatrix.sync.aligned.m8n8.x2.shared.b16 {%0,%1}, [%2];"
                 : "=r"(r[0]), "=r"(r[1]) : "r"(addr));
}
__device__ __forceinline__ void mma_bf16(float* d, const uint32_t* a, const uint32_t* b) {
    asm volatile(
        "mma.sync.aligned.m16n8k16.row.col.f32.bf16.bf16.f32 "
        "{%0,%1,%2,%3}, {%4,%5,%6,%7}, {%8,%9}, {%0,%1,%2,%3};"
        : "+f"(d[0]), "+f"(d[1]), "+f"(d[2]), "+f"(d[3])
        : "r"(a[0]), "r"(a[1]), "r"(a[2]), "r"(a[3]), "r"(b[0]), "r"(b[1]));
}

__device__ __forceinline__ float gelu_f(float x) {
    return 0.5f * x * (1.0f + erff(x * 0.7071067811865476f));
}

// ======================= mma.sync bf16-split GEMM =======================
// C[4096, N] = A[4096,K] @ B (+epilogue). CTA tile 128x128, 4 warps (64x64 each),
// K-chunk 32, split-bf16 (hi/lo), double-buffered smem, 1 sync/stage.
// EPI: 0=none, 1=+bias, 2=+bias+residual, 3=+bias then GELU
// BT:  0 = B is [K,N] row-major; 1 = B is [N,K] row-major (used transposed)
//
// TCSTRIDE must be a multiple of 16 (ldmatrix row-pointer alignment) and give a
// conflict-free 8-row phase pattern: 80*i mod 128 = {0,80,32,112,64,16,96,48}.
#define TCSTRIDE 80            // bytes per 32-element bf16 k-row (padded from 64)
#define REG_ALO  10240
#define REG_B    20480
#define REG_BLO  30720
#define STAGE_BYTES 40960
#define GEMM_SMEM (2 * STAGE_BYTES)

template <int EPI, int BT>
__global__ void __launch_bounds__(128) tc_gemm(const float* __restrict__ A,
                                               const float* __restrict__ B,
                                               const float* __restrict__ bias,
                                               const float* __restrict__ R,
                                               float* __restrict__ C,
                                               int N, int K) {
    extern __shared__ char sm[];
    const uint32_t sbase = smem_u32(sm);
    const int tid = threadIdx.x;
    const int warp = tid >> 5, lane = tid & 31;

    // m-inner tile order: consecutive CTAs share the same B block (L2 reuse of wte)
    const int m0 = (blockIdx.x & 31) * 128;
    const int n0 = (blockIdx.x >> 5) * 128;

    const int warpM = (warp >> 1) * 64;
    const int warpN = (warp & 1) * 64;

    float acc[4][8][4];
#pragma unroll
    for (int i = 0; i < 4; i++)
#pragma unroll
        for (int j = 0; j < 8; j++)
#pragma unroll
            for (int c = 0; c < 4; c++) acc[i][j][c] = 0.f;

    // per-lane ldmatrix sub-offsets (within tile region); 16B-aligned by construction
    const uint32_t aoff = (uint32_t)((warpM + (lane & 15)) * TCSTRIDE + ((lane >> 4) * 8) * 2);
    const uint32_t boff = (uint32_t)((warpN + (lane & 7)) * TCSTRIDE + (((lane >> 3) & 1) * 8) * 2);

    const int NK = K >> 5;
    for (int kt = 0; kt < NK; kt++) {
        const uint32_t st = sbase + (kt & 1) * STAGE_BYTES;
        const int k0 = kt << 5;

        // ---- fill A tile: 128 rows x 32 k (fp32 -> hi/lo bf16) ----
#pragma unroll
        for (int u = 0; u < 8; u++) {
            int f = tid + (u << 7);          // 0..1023
            int row = f >> 3;                // 0..127
            int kc = (f & 7) << 2;           // 0,4,..,28
            float4 v = *(const float4*)&A[(size_t)(m0 + row) * K + k0 + kc];
            uint32_t off = st + row * TCSTRIDE + (kc << 1);
            sts64(off,           packbf2(v.x, v.y), packbf2(v.z, v.w));
            sts64(off + REG_ALO, packbf2(v.x - bfh(v.x), v.y - bfh(v.y)),
                                 packbf2(v.z - bfh(v.z), v.w - bfh(v.w)));
        }

        // ---- fill B tile: 128 n-rows x 32 k ----
        if (BT) {
            // B = wte [N][K]; K-major rows, guard ragged N
#pragma unroll
            for (int u = 0; u < 8; u++) {
                int f = tid + (u << 7);
                int row = f >> 3;
                int kc = (f & 7) << 2;
                int gn = n0 + row;
                float4 v = make_float4(0.f, 0.f, 0.f, 0.f);
                if (gn < N) v = *(const float4*)&B[(size_t)gn * K + k0 + kc];
                uint32_t off = st + REG_B + row * TCSTRIDE + (kc << 1);
                sts64(off,                     packbf2(v.x, v.y), packbf2(v.z, v.w));
                sts64(off + (REG_BLO - REG_B), packbf2(v.x - bfh(v.x), v.y - bfh(v.y)),
                                               packbf2(v.z - bfh(v.z), v.w - bfh(v.w)));
            }
        } else {
            // B = W [K][N]; transpose into [n][k] (N multiple of 128 here)
#pragma unroll
            for (int u = 0; u < 8; u++) {
                int n = tid;                 // 0..127 (coalesced along n)
                int k4 = u << 2;             // 0,4,..,28
                const float* bp = &B[(size_t)(k0 + k4) * N + n0 + n];
                float b0 = bp[0];
                float b1 = bp[(size_t)N];
                float b2 = bp[2 * (size_t)N];
                float b3 = bp[3 * (size_t)N];
                uint32_t off = st + REG_B + n * TCSTRIDE + (k4 << 1);
                sts64(off,                     packbf2(b0, b1), packbf2(b2, b3));
                sts64(off + (REG_BLO - REG_B), packbf2(b0 - bfh(b0), b1 - bfh(b1)),
                                               packbf2(b2 - bfh(b2), b3 - bfh(b3)));
            }
        }

        __syncthreads();

        // ---- compute: 2 k16-steps x 3 split products ----
#pragma unroll
        for (int ks = 0; ks < 2; ks++) {
            uint32_t ahi[4][4], alo[4][4];
#pragma unroll
            for (int mt = 0; mt < 4; mt++) {
                uint32_t ad = st + aoff + mt * (16 * TCSTRIDE) + (ks * 16 * 2);
                ldsm_x4(ad, ahi[mt]);
                ldsm_x4(ad + REG_ALO, alo[mt]);
            }
#pragma unroll
            for (int nh = 0; nh < 2; nh++) {
                uint32_t bhi[4][2], blo[4][2];
#pragma unroll
                for (int j = 0; j < 4; j++) {
                    uint32_t bd = st + REG_B + boff + (nh * 4 + j) * (8 * TCSTRIDE) + (ks * 16 * 2);
                    ldsm_x2(bd, bhi[j]);
                    ldsm_x2(bd + (REG_BLO - REG_B), blo[j]);
                }
                // hi*hi
#pragma unroll
                for (int mt = 0; mt < 4; mt++)
#pragma unroll
                    for (int j = 0; j < 4; j++)
                        mma_bf16(acc[mt][nh * 4 + j], ahi[mt], bhi[j]);
                // hi*lo
#pragma unroll
                for (int mt = 0; mt < 4; mt++)
#pragma unroll
                    for (int j = 0; j < 4; j++)
                        mma_bf16(acc[mt][nh * 4 + j], ahi[mt], blo[j]);
                // lo*hi
#pragma unroll
                for (int mt = 0; mt < 4; mt++)
#pragma unroll
                    for (int j = 0; j < 4; j++)
                        mma_bf16(acc[mt][nh * 4 + j], alo[mt], bhi[j]);
            }
        }
        // no trailing sync needed: next fill targets the other buffer, and
        // fill(kt+2) is ordered after compute(kt) via sync(kt+1).
    }

    // ---- epilogue ----
    const int g = lane >> 2, t4 = lane & 3;
#pragma unroll
    for (int mt = 0; mt < 4; mt++) {
#pragma unroll
        for (int nt = 0; nt < 8; nt++) {
            int col = n0 + warpN + nt * 8 + 2 * t4;
            int row0 = m0 + warpM + mt * 16 + g;
#pragma unroll
            for (int h = 0; h < 2; h++) {   // h=0: rows g, h=1: rows g+8
                int rowg = row0 + h * 8;
                float v0 = acc[mt][nt][2 * h];
                float v1 = acc[mt][nt][2 * h + 1];
                if (BT == 1) {
                    // ragged N: scalar guarded stores
                    if (col < N) {
                        if (EPI >= 1) v0 += bias[col];
                        C[(size_t)rowg * N + col] = v0;
                    }
                    if (col + 1 < N) {
                        if (EPI >= 1) v1 += bias[col + 1];
                        C[(size_t)rowg * N + col + 1] = v1;
                    }
                } else {
                    if (EPI >= 1) { v0 += bias[col]; v1 += bias[col + 1]; }
                    if (EPI == 2) {
                        v0 += R[(size_t)rowg * N + col];
                        v1 += R[(size_t)rowg * N + col + 1];
                    }
                    if (EPI == 3) { v0 = gelu_f(v0); v1 = gelu_f(v1); }
                    float2 o = make_float2(v0, v1);
                    *(float2*)&C[(size_t)rowg * N + col] = o;
                }
            }
        }
    }
}

// ---------------- embedding: x = wte[idx] + wpe[t] ----------------
__global__ void embed_kernel(const int* __restrict__ idx,
                             const float* __restrict__ wte,
                             const float* __restrict__ wpe,
                             float* __restrict__ x) {
    int i = blockIdx.x * blockDim.x + threadIdx.x;
    if (i >= MROW * EMB) return;
    int row = i / EMB;
    int e = i - row * EMB;
    int t = row % TLEN;
    x[i] = wte[(size_t)idx[row] * EMB + e] + wpe[(size_t)t * EMB + e];
}

// ---------------- layernorm: one block (256 thr) per row of 768 ----------------
__global__ void __launch_bounds__(256) ln_kernel(const float* __restrict__ x,
                                                 const float* __restrict__ w,
                                                 const float* __restrict__ b,
                                                 float* __restrict__ out) {
    __shared__ float red[8];
    __shared__ float s_mean, s_var;
    int row = blockIdx.x;
    int tid = threadIdx.x;
    int warp = tid >> 5, lane = tid & 31;
    const float* xr = x + (size_t)row * EMB;

    float v0 = xr[tid], v1 = xr[tid + 256], v2 = xr[tid + 512];
    float s = v0 + v1 + v2;
#pragma unroll
    for (int o = 16; o; o >>= 1) s += __shfl_xor_sync(0xffffffffu, s, o);
    if (lane == 0) red[warp] = s;
    __syncthreads();
    if (tid == 0) {
        float t = 0.f;
#pragma unroll
        for (int i = 0; i < 8; i++) t += red[i];
        s_mean = t * (1.0f / EMB);
    }
    __syncthreads();
    float m = s_mean;
    float d0 = v0 - m, d1 = v1 - m, d2 = v2 - m;
    float q = d0 * d0 + d1 * d1 + d2 * d2;
#pragma unroll
    for (int o = 16; o; o >>= 1) q += __shfl_xor_sync(0xffffffffu, q, o);
    if (lane == 0) red[warp] = q;
    __syncthreads();
    if (tid == 0) {
        float t = 0.f;
#pragma unroll
        for (int i = 0; i < 8; i++) t += red[i];
        s_var = t * (1.0f / EMB);
    }
    __syncthreads();
    float r = rsqrtf(s_var + 1e-5f);
    float* orow = out + (size_t)row * EMB;
    orow[tid]       = d0 * r * w[tid]       + b[tid];
    orow[tid + 256] = d1 * r * w[tid + 256] + b[tid + 256];
    orow[tid + 512] = d2 * r * w[tid + 512] + b[tid + 512];
}

// ---------------- attention: warp-per-query online softmax ----------------
__global__ void __launch_bounds__(256) attn_kernel(const float* __restrict__ qkv,
                                                   float* __restrict__ y) {
    __shared__ float Ks[64][64];
    __shared__ float Vs[64][64];
    int bh = blockIdx.x;
    int b = bh / NHEAD, h = bh % NHEAD;
    int q0 = blockIdx.y * 8;
    int warp = threadIdx.x >> 5, lane = threadIdx.x & 31;
    int q = q0 + warp;

    size_t qbase = ((size_t)(b * TLEN + q)) * (3 * EMB) + h * HEADD;
    float2 qv = *(const float2*)&qkv[qbase + 2 * lane];

    float m = -1e30f, lsum = 0.f, ax = 0.f, ay = 0.f;
    int nch = q0 / 64 + 1;

    for (int c = 0; c < nch; c++) {
        int kb = c * 64;
        for (int i = threadIdx.x; i < 64 * 64; i += 256) {
            int kk = i >> 6, d = i & 63;
            size_t base = ((size_t)(b * TLEN + kb + kk)) * (3 * EMB) + h * HEADD + d;
            Ks[kk][d] = qkv[base + EMB];
            Vs[kk][d] = qkv[base + 2 * EMB];
        }
        __syncthreads();

        int jmax = q - kb;
        if (jmax > 63) jmax = 63;
        for (int j = 0; j <= jmax; j++) {
            float s = qv.x * Ks[j][2 * lane] + qv.y * Ks[j][2 * lane + 1];
#pragma unroll
            for (int o = 16; o; o >>= 1) s += __shfl_xor_sync(0xffffffffu, s, o);
            s *= 0.125f;
            float mn = fmaxf(m, s);
            float corr = __expf(m - mn);
            float p = __expf(s - mn);
            ax = ax * corr + p * Vs[j][2 * lane];
            ay = ay * corr + p * Vs[j][2 * lane + 1];
            lsum = lsum * corr + p;
            m = mn;
        }
        __syncthreads();
    }

    float inv = 1.0f / lsum;
    float2 o2 = make_float2(ax * inv, ay * inv);
    *(float2*)&y[((size_t)(b * TLEN + q)) * EMB + h * HEADD + 2 * lane] = o2;
}

// ---------------- host launch ----------------
extern "C" void kernel_launch(void* const* d_in, const int* in_sizes, int n_in,
                              void* d_out, int out_size) {
    (void)in_sizes; (void)n_in; (void)out_size;
    const int*   x_idx  = (const int*)d_in[0];
    const float* wte    = (const float*)d_in[1];
    const float* wpe    = (const float*)d_in[2];
    const float* ln1_w  = (const float*)d_in[3];
    const float* ln1_b  = (const float*)d_in[4];
    const float* attn_w = (const float*)d_in[5];
    const float* attn_b = (const float*)d_in[6];
    const float* proj_w = (const float*)d_in[7];
    const float* proj_b = (const float*)d_in[8];
    const float* ln2_w  = (const float*)d_in[9];
    const float* ln2_b  = (const float*)d_in[10];
    const float* fc1_w  = (const float*)d_in[11];
    const float* fc1_b  = (const float*)d_in[12];
    const float* fc2_w  = (const float*)d_in[13];
    const float* fc2_b  = (const float*)d_in[14];
    const float* lnf_w  = (const float*)d_in[15];
    const float* lnf_b  = (const float*)d_in[16];
    float* out = (float*)d_out;

    float *gx, *gh, *gqkv, *gy, *gfc1;
    cudaGetSymbolAddress((void**)&gx,   g_x);
    cudaGetSymbolAddress((void**)&gh,   g_h);
    cudaGetSymbolAddress((void**)&gqkv, g_qkv);
    cudaGetSymbolAddress((void**)&gy,   g_y);
    cudaGetSymbolAddress((void**)&gfc1, g_fc1);

    cudaFuncSetAttribute(tc_gemm<1, 0>, cudaFuncAttributeMaxDynamicSharedMemorySize, GEMM_SMEM);
    cudaFuncSetAttribute(tc_gemm<2, 0>, cudaFuncAttributeMaxDynamicSharedMemorySize, GEMM_SMEM);
    cudaFuncSetAttribute(tc_gemm<3, 0>, cudaFuncAttributeMaxDynamicSharedMemorySize, GEMM_SMEM);
    cudaFuncSetAttribute(tc_gemm<0, 1>, cudaFuncAttributeMaxDynamicSharedMemorySize, GEMM_SMEM);

    embed_kernel<<<(MROW * EMB + 255) / 256, 256>>>(x_idx, wte, wpe, gx);

    for (int l = 0; l < NLAYER; l++) {
        ln_kernel<<<MROW, 256>>>(gx, ln1_w + (size_t)l * EMB, ln1_b + (size_t)l * EMB, gh);

        // qkv = h @ attn_w + attn_b     (N=2304 -> 18 n-tiles)
        tc_gemm<1, 0><<<32 * 18, 128, GEMM_SMEM>>>(
            gh, attn_w + (size_t)l * EMB * 3 * EMB, attn_b + (size_t)l * 3 * EMB,
            nullptr, gqkv, 3 * EMB, EMB);

        attn_kernel<<<dim3(BATCH * NHEAD, TLEN / 8), 256>>>(gqkv, gy);

        // x = x + y @ proj_w + proj_b   (N=768 -> 6 n-tiles)
        tc_gemm<2, 0><<<32 * 6, 128, GEMM_SMEM>>>(
            gy, proj_w + (size_t)l * EMB * EMB, proj_b + (size_t)l * EMB,
            gx, gx, EMB, EMB);

        ln_kernel<<<MROW, 256>>>(gx, ln2_w + (size_t)l * EMB, ln2_b + (size_t)l * EMB, gh);

        // fc1 = gelu(h @ fc1_w + fc1_b) (N=3072 -> 24 n-tiles)
        tc_gemm<3, 0><<<32 * 24, 128, GEMM_SMEM>>>(
            gh, fc1_w + (size_t)l * EMB * 4 * EMB, fc1_b + (size_t)l * 4 * EMB,
            nullptr, gfc1, 4 * EMB, EMB);

        // x = x + fc1 @ fc2_w + fc2_b   (N=768, K=3072 -> 6 n-tiles)
        tc_gemm<2, 0><<<32 * 6, 128, GEMM_SMEM>>>(
            gfc1, fc2_w + (size_t)l * 4 * EMB * EMB, fc2_b + (size_t)l * EMB,
            gx, gx, EMB, 4 * EMB);
    }

    ln_kernel<<<MROW, 256>>>(gx, lnf_w, lnf_b, gh);

    // logits = h @ wte^T   (N=50257 -> 393 n-tiles, B transposed)
    tc_gemm<0, 1><<<32 * 393, 128, GEMM_SMEM>>>(
        gh, wte, nullptr, nullptr, out, VOCAB, EMB);
}

// round 9
// speedup vs baseline: 1.9144x; 1.0398x over previous
#include <cuda_runtime.h>
#include <cuda_bf16.h>
#include <math.h>
#include <stdint.h>

// GPT-2 small config
#define BATCH 4
#define TLEN  1024
#define EMB   768
#define NLAYER 12
#define VOCAB 50257
#define NHEAD 12
#define HEADD 64
#define MROW  (BATCH * TLEN)   // 4096

// ---------------- scratch (device globals; no allocation allowed) ----------------
__device__ float g_x[MROW * EMB];        // residual stream (fp32)
__device__ float g_qkv[MROW * 3 * EMB];  // qkv projection (fp32, attn consumer)

// split-bf16 activations (produced by LN / attn / fc1-gelu epilogues)
__device__ __nv_bfloat16 g_h_hi[MROW * EMB],     g_h_lo[MROW * EMB];
__device__ __nv_bfloat16 g_y_hi[MROW * EMB],     g_y_lo[MROW * EMB];
__device__ __nv_bfloat16 g_f1_hi[MROW * 4 * EMB], g_f1_lo[MROW * 4 * EMB];

// split-bf16 weights, stored [N][K] (K-major rows) for ldmatrix col access
__device__ __nv_bfloat16 g_wqkv_hi[NLAYER * 3 * EMB * EMB], g_wqkv_lo[NLAYER * 3 * EMB * EMB];
__device__ __nv_bfloat16 g_wproj_hi[NLAYER * EMB * EMB],    g_wproj_lo[NLAYER * EMB * EMB];
__device__ __nv_bfloat16 g_wf1_hi[NLAYER * 4 * EMB * EMB],  g_wf1_lo[NLAYER * 4 * EMB * EMB];
__device__ __nv_bfloat16 g_wf2_hi[NLAYER * 4 * EMB * EMB],  g_wf2_lo[NLAYER * 4 * EMB * EMB];
__device__ __nv_bfloat16 g_wte_hi[VOCAB * EMB],             g_wte_lo[VOCAB * EMB];

// ======================= helpers =======================
__device__ __forceinline__ uint32_t smem_u32(const void* p) {
    uint32_t a;
    asm("{ .reg .u64 t; cvta.to.shared.u64 t, %1; cvt.u32.u64 %0, t; }"
        : "=r"(a) : "l"(p));
    return a;
}
__device__ __forceinline__ void ldsm_x4(uint32_t addr, uint32_t* r) {
    asm volatile("ldmatrix.sync.aligned.m8n8.x4.shared.b16 {%0,%1,%2,%3}, [%4];"
                 : "=r"(r[0]), "=r"(r[1]), "=r"(r[2]), "=r"(r[3]) : "r"(addr));
}
__device__ __forceinline__ void ldsm_x2(uint32_t addr, uint32_t* r) {
    asm volatile("ldmatrix.sync.aligned.m8n8.x2.shared.b16 {%0,%1}, [%2];"
                 : "=r"(r[0]), "=r"(r[1]) : "r"(addr));
}
__device__ __forceinline__ void mma_bf16(float* d, const uint32_t* a, const uint32_t* b) {
    asm volatile(
        "mma.sync.aligned.m16n8k16.row.col.f32.bf16.bf16.f32 "
        "{%0,%1,%2,%3}, {%4,%5,%6,%7}, {%8,%9}, {%0,%1,%2,%3};"
        : "+f"(d[0]), "+f"(d[1]), "+f"(d[2]), "+f"(d[3])
        : "r"(a[0]), "r"(a[1]), "r"(a[2]), "r"(a[3]), "r"(b[0]), "r"(b[1]));
}
__device__ __forceinline__ void cp16(uint32_t saddr, const void* g) {
    asm volatile("cp.async.cg.shared.global [%0], [%1], 16;" :: "r"(saddr), "l"(g));
}
__device__ __forceinline__ void cp16z(uint32_t saddr, const void* g, int ok) {
    int sz = ok ? 16 : 0;
    asm volatile("cp.async.cg.shared.global [%0], [%1], 16, %2;" :: "r"(saddr), "l"(g), "r"(sz));
}
#define CP_COMMIT() asm volatile("cp.async.commit_group;" ::: "memory")
#define CP_WAIT1()  asm volatile("cp.async.wait_group 1;" ::: "memory")

__device__ __forceinline__ float gelu_f(float x) {
    return 0.5f * x * (1.0f + erff(x * 0.7071067811865476f));
}

// ======================= weight pre-split kernels =======================
// elementwise split (no transpose): wte [V][E] is already K-major per row
__global__ void split_kernel(const float* __restrict__ src,
                             __nv_bfloat16* __restrict__ dhi,
                             __nv_bfloat16* __restrict__ dlo, int n) {
    int i = blockIdx.x * blockDim.x + threadIdx.x;
    if (i >= n) return;
    float v = src[i];
    __nv_bfloat16 h = __float2bfloat16_rn(v);
    dhi[i] = h;
    dlo[i] = __float2bfloat16_rn(v - __bfloat162float(h));
}

// transpose+split: src [K][N] fp32 -> dst [N][K] bf16 hi/lo. K,N multiples of 32.
__global__ void __launch_bounds__(256) splitT_kernel(const float* __restrict__ src,
                                                     __nv_bfloat16* __restrict__ dhi,
                                                     __nv_bfloat16* __restrict__ dlo,
                                                     int K, int N) {
    __shared__ float t[32][33];
    int tx = threadIdx.x & 31, ty = threadIdx.x >> 5;  // 32 x 8
    int bn = blockIdx.x * 32, bk = blockIdx.y * 32;
#pragma unroll
    for (int i = 0; i < 4; i++)
        t[ty + i * 8][tx] = src[(size_t)(bk + ty + i * 8) * N + bn + tx];
    __syncthreads();
#pragma unroll
    for (int i = 0; i < 4; i++) {
        int n = bn + ty + i * 8;
        int k = bk + tx;
        float v = t[tx][ty + i * 8];
        __nv_bfloat16 h = __float2bfloat16_rn(v);
        dhi[(size_t)n * K + k] = h;
        dlo[(size_t)n * K + k] = __float2bfloat16_rn(v - __bfloat162float(h));
    }
}

// ======================= mma.sync bf16-split GEMM (pre-split inputs) =======================
// C[4096, N] = (Ahi+Alo)[M][K] @ (Bhi+Blo)[N][K]^T, 3 products hi*hi+hi*lo+lo*hi.
// CTA tile 128x128, 4 warps (64x64), K-chunk 32, cp.async double buffer.
// EPI: 0=none(fp32 C), 1=+bias(fp32 C), 2=+bias+residual(fp32 C), 3=+bias,GELU -> split out
// RAGGED: guard B rows / C cols against N (lm_head)
#define TCSTRIDE 80
#define REG_ALO  10240
#define REG_B    20480
#define REG_BLO  30720
#define STAGE_BYTES 40960
#define GEMM_SMEM (2 * STAGE_BYTES)

template <int EPI, int RAGGED>
__global__ void __launch_bounds__(128) tc_gemm(const __nv_bfloat16* __restrict__ Ahi,
                                               const __nv_bfloat16* __restrict__ Alo,
                                               const __nv_bfloat16* __restrict__ Bhi,
                                               const __nv_bfloat16* __restrict__ Blo,
                                               const float* __restrict__ bias,
                                               const float* __restrict__ R,
                                               float* __restrict__ C,
                                               __nv_bfloat16* __restrict__ Chi,
                                               __nv_bfloat16* __restrict__ Clo,
                                               int N, int K) {
    extern __shared__ char sm[];
    const uint32_t sbase = smem_u32(sm);
    const int tid = threadIdx.x;
    const int warp = tid >> 5, lane = tid & 31;

    // m-inner ordering: consecutive CTAs share the same B tile (L2 reuse)
    const int m0 = (blockIdx.x & 31) * 128;
    const int n0 = (blockIdx.x >> 5) * 128;

    const int warpM = (warp >> 1) * 64;
    const int warpN = (warp & 1) * 64;

    float acc[4][8][4];
#pragma unroll
    for (int i = 0; i < 4; i++)
#pragma unroll
        for (int j = 0; j < 8; j++)
#pragma unroll
            for (int c = 0; c < 4; c++) acc[i][j][c] = 0.f;

    // per-thread fill slots: id = tid*? -> 512 chunks per region; row = id>>2, c = id&3
    int frow[4], fc[4];
#pragma unroll
    for (int u = 0; u < 4; u++) {
        int id = tid + (u << 7);
        frow[u] = id >> 2;
        fc[u] = id & 3;
    }

    const int NK = K >> 5;

    // fill stage s into buffer s&1
    auto fill = [&](int s) {
        const uint32_t st = sbase + (s & 1) * STAGE_BYTES;
        const int k0 = s << 5;
#pragma unroll
        for (int u = 0; u < 4; u++) {
            int row = frow[u], c = fc[u];
            uint32_t so = st + row * TCSTRIDE + c * 16;
            size_t ga = (size_t)(m0 + row) * K + k0 + c * 8;
            cp16(so, Ahi + ga);
            cp16(so + REG_ALO, Alo + ga);
            int gn = n0 + row;
            if (RAGGED) {
                int ok = gn < N;
                int gnc = ok ? gn : 0;
                size_t gb = (size_t)gnc * K + k0 + c * 8;
                cp16z(so + REG_B, Bhi + gb, ok);
                cp16z(so + REG_BLO, Blo + gb, ok);
            } else {
                size_t gb = (size_t)gn * K + k0 + c * 8;
                cp16(so + REG_B, Bhi + gb);
                cp16(so + REG_BLO, Blo + gb);
            }
        }
    };

    fill(0); CP_COMMIT();
    fill(1); CP_COMMIT();

    const uint32_t aoff = (uint32_t)((warpM + (lane & 15)) * TCSTRIDE + ((lane >> 4) * 8) * 2);
    const uint32_t boff = (uint32_t)((warpN + (lane & 7)) * TCSTRIDE + (((lane >> 3) & 1) * 8) * 2);

    for (int kt = 0; kt < NK; kt++) {
        CP_WAIT1();
        __syncthreads();
        const uint32_t st = sbase + (kt & 1) * STAGE_BYTES;

#pragma unroll
        for (int ks = 0; ks < 2; ks++) {
            uint32_t ahi[4][4], alo[4][4];
#pragma unroll
            for (int mt = 0; mt < 4; mt++) {
                uint32_t ad = st + aoff + mt * (16 * TCSTRIDE) + (ks * 32);
                ldsm_x4(ad, ahi[mt]);
                ldsm_x4(ad + REG_ALO, alo[mt]);
            }
#pragma unroll
            for (int nh = 0; nh < 2; nh++) {
                uint32_t bhi[4][2], blo[4][2];
#pragma unroll
                for (int j = 0; j < 4; j++) {
                    uint32_t bd = st + REG_B + boff + (nh * 4 + j) * (8 * TCSTRIDE) + (ks * 32);
                    ldsm_x2(bd, bhi[j]);
                    ldsm_x2(bd + (REG_BLO - REG_B), blo[j]);
                }
#pragma unroll
                for (int mt = 0; mt < 4; mt++)
#pragma unroll
                    for (int j = 0; j < 4; j++)
                        mma_bf16(acc[mt][nh * 4 + j], ahi[mt], bhi[j]);
#pragma unroll
                for (int mt = 0; mt < 4; mt++)
#pragma unroll
                    for (int j = 0; j < 4; j++)
                        mma_bf16(acc[mt][nh * 4 + j], ahi[mt], blo[j]);
#pragma unroll
                for (int mt = 0; mt < 4; mt++)
#pragma unroll
                    for (int j = 0; j < 4; j++)
                        mma_bf16(acc[mt][nh * 4 + j], alo[mt], bhi[j]);
            }
        }
        __syncthreads();
        if (kt + 2 < NK) fill(kt + 2);
        CP_COMMIT();
    }

    // ---- epilogue ----
    const int g = lane >> 2, t4 = lane & 3;
#pragma unroll
    for (int mt = 0; mt < 4; mt++) {
#pragma unroll
        for (int nt = 0; nt < 8; nt++) {
            int col = n0 + warpN + nt * 8 + 2 * t4;
            int row0 = m0 + warpM + mt * 16 + g;
#pragma unroll
            for (int h = 0; h < 2; h++) {
                int rowg = row0 + h * 8;
                float v0 = acc[mt][nt][2 * h];
                float v1 = acc[mt][nt][2 * h + 1];
                if (RAGGED) {
                    if (col < N) {
                        if (EPI >= 1) v0 += bias[col];
                        C[(size_t)rowg * N + col] = v0;
                    }
                    if (col + 1 < N) {
                        if (EPI >= 1) v1 += bias[col + 1];
                        C[(size_t)rowg * N + col + 1] = v1;
                    }
                } else if (EPI == 3) {
                    v0 = gelu_f(v0 + bias[col]);
                    v1 = gelu_f(v1 + bias[col + 1]);
                    __nv_bfloat16 h0 = __float2bfloat16_rn(v0);
                    __nv_bfloat16 h1 = __float2bfloat16_rn(v1);
                    __nv_bfloat16 l0 = __float2bfloat16_rn(v0 - __bfloat162float(h0));
                    __nv_bfloat16 l1 = __float2bfloat16_rn(v1 - __bfloat162float(h1));
                    size_t o = (size_t)rowg * N + col;
                    *(__nv_bfloat162*)&Chi[o] = __halves2bfloat162(h0, h1);
                    *(__nv_bfloat162*)&Clo[o] = __halves2bfloat162(l0, l1);
                } else {
                    if (EPI >= 1) { v0 += bias[col]; v1 += bias[col + 1]; }
                    if (EPI == 2) {
                        v0 += R[(size_t)rowg * N + col];
                        v1 += R[(size_t)rowg * N + col + 1];
                    }
                    float2 o = make_float2(v0, v1);
                    *(float2*)&C[(size_t)rowg * N + col] = o;
                }
            }
        }
    }
}

// ---------------- embedding: x = wte[idx] + wpe[t] ----------------
__global__ void embed_kernel(const int* __restrict__ idx,
                             const float* __restrict__ wte,
                             const float* __restrict__ wpe,
                             float* __restrict__ x) {
    int i = blockIdx.x * blockDim.x + threadIdx.x;
    if (i >= MROW * EMB) return;
    int row = i / EMB;
    int e = i - row * EMB;
    int t = row % TLEN;
    x[i] = wte[(size_t)idx[row] * EMB + e] + wpe[(size_t)t * EMB + e];
}

// ---------------- layernorm: fp32 in, split-bf16 out ----------------
__global__ void __launch_bounds__(256) ln_kernel(const float* __restrict__ x,
                                                 const float* __restrict__ w,
                                                 const float* __restrict__ b,
                                                 __nv_bfloat16* __restrict__ ohi,
                                                 __nv_bfloat16* __restrict__ olo) {
    __shared__ float red[8];
    __shared__ float s_mean, s_var;
    int row = blockIdx.x;
    int tid = threadIdx.x;
    int warp = tid >> 5, lane = tid & 31;
    const float* xr = x + (size_t)row * EMB;

    float v0 = xr[tid], v1 = xr[tid + 256], v2 = xr[tid + 512];
    float s = v0 + v1 + v2;
#pragma unroll
    for (int o = 16; o; o >>= 1) s += __shfl_xor_sync(0xffffffffu, s, o);
    if (lane == 0) red[warp] = s;
    __syncthreads();
    if (tid == 0) {
        float t = 0.f;
#pragma unroll
        for (int i = 0; i < 8; i++) t += red[i];
        s_mean = t * (1.0f / EMB);
    }
    __syncthreads();
    float m = s_mean;
    float d0 = v0 - m, d1 = v1 - m, d2 = v2 - m;
    float q = d0 * d0 + d1 * d1 + d2 * d2;
#pragma unroll
    for (int o = 16; o; o >>= 1) q += __shfl_xor_sync(0xffffffffu, q, o);
    if (lane == 0) red[warp] = q;
    __syncthreads();
    if (tid == 0) {
        float t = 0.f;
#pragma unroll
        for (int i = 0; i < 8; i++) t += red[i];
        s_var = t * (1.0f / EMB);
    }
    __syncthreads();
    float r = rsqrtf(s_var + 1e-5f);
    size_t base = (size_t)row * EMB;
#pragma unroll
    for (int u = 0; u < 3; u++) {
        int e = tid + u * 256;
        float d = (u == 0 ? d0 : (u == 1 ? d1 : d2));
        float v = d * r * w[e] + b[e];
        __nv_bfloat16 h = __float2bfloat16_rn(v);
        ohi[base + e] = h;
        olo[base + e] = __float2bfloat16_rn(v - __bfloat162float(h));
    }
}

// ---------------- attention: warp-per-query online softmax, split-bf16 out ----------------
__global__ void __launch_bounds__(256) attn_kernel(const float* __restrict__ qkv,
                                                   __nv_bfloat16* __restrict__ yhi,
                                                   __nv_bfloat16* __restrict__ ylo) {
    __shared__ float Ks[64][64];
    __shared__ float Vs[64][64];
    int bh = blockIdx.x;
    int b = bh / NHEAD, h = bh % NHEAD;
    int q0 = blockIdx.y * 8;
    int warp = threadIdx.x >> 5, lane = threadIdx.x & 31;
    int q = q0 + warp;

    size_t qbase = ((size_t)(b * TLEN + q)) * (3 * EMB) + h * HEADD;
    float2 qv = *(const float2*)&qkv[qbase + 2 * lane];

    float m = -1e30f, lsum = 0.f, ax = 0.f, ay = 0.f;
    int nch = q0 / 64 + 1;

    for (int c = 0; c < nch; c++) {
        int kb = c * 64;
        for (int i = threadIdx.x; i < 64 * 64; i += 256) {
            int kk = i >> 6, d = i & 63;
            size_t base = ((size_t)(b * TLEN + kb + kk)) * (3 * EMB) + h * HEADD + d;
            Ks[kk][d] = qkv[base + EMB];
            Vs[kk][d] = qkv[base + 2 * EMB];
        }
        __syncthreads();

        int jmax = q - kb;
        if (jmax > 63) jmax = 63;
        for (int j = 0; j <= jmax; j++) {
            float s = qv.x * Ks[j][2 * lane] + qv.y * Ks[j][2 * lane + 1];
#pragma unroll
            for (int o = 16; o; o >>= 1) s += __shfl_xor_sync(0xffffffffu, s, o);
            s *= 0.125f;
            float mn = fmaxf(m, s);
            float corr = __expf(m - mn);
            float p = __expf(s - mn);
            ax = ax * corr + p * Vs[j][2 * lane];
            ay = ay * corr + p * Vs[j][2 * lane + 1];
            lsum = lsum * corr + p;
            m = mn;
        }
        __syncthreads();
    }

    float inv = 1.0f / lsum;
    float vx = ax * inv, vy = ay * inv;
    __nv_bfloat16 hx = __float2bfloat16_rn(vx);
    __nv_bfloat16 hy = __float2bfloat16_rn(vy);
    __nv_bfloat16 lx = __float2bfloat16_rn(vx - __bfloat162float(hx));
    __nv_bfloat16 ly = __float2bfloat16_rn(vy - __bfloat162float(hy));
    size_t o = ((size_t)(b * TLEN + q)) * EMB + h * HEADD + 2 * lane;
    *(__nv_bfloat162*)&yhi[o] = __halves2bfloat162(hx, hy);
    *(__nv_bfloat162*)&ylo[o] = __halves2bfloat162(lx, ly);
}

// ---------------- host launch ----------------
extern "C" void kernel_launch(void* const* d_in, const int* in_sizes, int n_in,
                              void* d_out, int out_size) {
    (void)in_sizes; (void)n_in; (void)out_size;
    const int*   x_idx  = (const int*)d_in[0];
    const float* wte    = (const float*)d_in[1];
    const float* wpe    = (const float*)d_in[2];
    const float* ln1_w  = (const float*)d_in[3];
    const float* ln1_b  = (const float*)d_in[4];
    const float* attn_w = (const float*)d_in[5];
    const float* attn_b = (const float*)d_in[6];
    const float* proj_w = (const float*)d_in[7];
    const float* proj_b = (const float*)d_in[8];
    const float* ln2_w  = (const float*)d_in[9];
    const float* ln2_b  = (const float*)d_in[10];
    const float* fc1_w  = (const float*)d_in[11];
    const float* fc1_b  = (const float*)d_in[12];
    const float* fc2_w  = (const float*)d_in[13];
    const float* fc2_b  = (const float*)d_in[14];
    const float* lnf_w  = (const float*)d_in[15];
    const float* lnf_b  = (const float*)d_in[16];
    float* out = (float*)d_out;

    float *gx, *gqkv;
    __nv_bfloat16 *hhi, *hlo, *yhi, *ylo, *f1hi, *f1lo;
    __nv_bfloat16 *wqh, *wql, *wph, *wpl, *w1h, *w1l, *w2h, *w2l, *wth, *wtl;
    cudaGetSymbolAddress((void**)&gx,   g_x);
    cudaGetSymbolAddress((void**)&gqkv, g_qkv);
    cudaGetSymbolAddress((void**)&hhi,  g_h_hi);
    cudaGetSymbolAddress((void**)&hlo,  g_h_lo);
    cudaGetSymbolAddress((void**)&yhi,  g_y_hi);
    cudaGetSymbolAddress((void**)&ylo,  g_y_lo);
    cudaGetSymbolAddress((void**)&f1hi, g_f1_hi);
    cudaGetSymbolAddress((void**)&f1lo, g_f1_lo);
    cudaGetSymbolAddress((void**)&wqh,  g_wqkv_hi);
    cudaGetSymbolAddress((void**)&wql,  g_wqkv_lo);
    cudaGetSymbolAddress((void**)&wph,  g_wproj_hi);
    cudaGetSymbolAddress((void**)&wpl,  g_wproj_lo);
    cudaGetSymbolAddress((void**)&w1h,  g_wf1_hi);
    cudaGetSymbolAddress((void**)&w1l,  g_wf1_lo);
    cudaGetSymbolAddress((void**)&w2h,  g_wf2_hi);
    cudaGetSymbolAddress((void**)&w2l,  g_wf2_lo);
    cudaGetSymbolAddress((void**)&wth,  g_wte_hi);
    cudaGetSymbolAddress((void**)&wtl,  g_wte_lo);

    cudaFuncSetAttribute(tc_gemm<1, 0>, cudaFuncAttributeMaxDynamicSharedMemorySize, GEMM_SMEM);
    cudaFuncSetAttribute(tc_gemm<2, 0>, cudaFuncAttributeMaxDynamicSharedMemorySize, GEMM_SMEM);
    cudaFuncSetAttribute(tc_gemm<3, 0>, cudaFuncAttributeMaxDynamicSharedMemorySize, GEMM_SMEM);
    cudaFuncSetAttribute(tc_gemm<0, 1>, cudaFuncAttributeMaxDynamicSharedMemorySize, GEMM_SMEM);

    // ---- pre-split weights (once per replay) ----
    split_kernel<<<(VOCAB * EMB + 255) / 256, 256>>>(wte, wth, wtl, VOCAB * EMB);
    for (int l = 0; l < NLAYER; l++) {
        splitT_kernel<<<dim3(3 * EMB / 32, EMB / 32), 256>>>(
            attn_w + (size_t)l * EMB * 3 * EMB,
            wqh + (size_t)l * 3 * EMB * EMB, wql + (size_t)l * 3 * EMB * EMB, EMB, 3 * EMB);
        splitT_kernel<<<dim3(EMB / 32, EMB / 32), 256>>>(
            proj_w + (size_t)l * EMB * EMB,
            wph + (size_t)l * EMB * EMB, wpl + (size_t)l * EMB * EMB, EMB, EMB);
        splitT_kernel<<<dim3(4 * EMB / 32, EMB / 32), 256>>>(
            fc1_w + (size_t)l * EMB * 4 * EMB,
            w1h + (size_t)l * 4 * EMB * EMB, w1l + (size_t)l * 4 * EMB * EMB, EMB, 4 * EMB);
        splitT_kernel<<<dim3(EMB / 32, 4 * EMB / 32), 256>>>(
            fc2_w + (size_t)l * 4 * EMB * EMB,
            w2h + (size_t)l * 4 * EMB * EMB, w2l + (size_t)l * 4 * EMB * EMB, 4 * EMB, EMB);
    }

    embed_kernel<<<(MROW * EMB + 255) / 256, 256>>>(x_idx, wte, wpe, gx);

    for (int l = 0; l < NLAYER; l++) {
        ln_kernel<<<MROW, 256>>>(gx, ln1_w + (size_t)l * EMB, ln1_b + (size_t)l * EMB, hhi, hlo);

        // qkv = h @ attn_w + attn_b    (N=2304 -> 18 n-tiles)
        tc_gemm<1, 0><<<32 * 18, 128, GEMM_SMEM>>>(
            hhi, hlo, wqh + (size_t)l * 3 * EMB * EMB, wql + (size_t)l * 3 * EMB * EMB,
            attn_b + (size_t)l * 3 * EMB, nullptr, gqkv, nullptr, nullptr, 3 * EMB, EMB);

        attn_kernel<<<dim3(BATCH * NHEAD, TLEN / 8), 256>>>(gqkv, yhi, ylo);

        // x = x + y @ proj_w + proj_b  (N=768 -> 6 n-tiles)
        tc_gemm<2, 0><<<32 * 6, 128, GEMM_SMEM>>>(
            yhi, ylo, wph + (size_t)l * EMB * EMB, wpl + (size_t)l * EMB * EMB,
            proj_b + (size_t)l * EMB, gx, gx, nullptr, nullptr, EMB, EMB);

        ln_kernel<<<MROW, 256>>>(gx, ln2_w + (size_t)l * EMB, ln2_b + (size_t)l * EMB, hhi, hlo);

        // f1 = gelu(h @ fc1_w + fc1_b) -> split bf16  (N=3072 -> 24 n-tiles)
        tc_gemm<3, 0><<<32 * 24, 128, GEMM_SMEM>>>(
            hhi, hlo, w1h + (size_t)l * 4 * EMB * EMB, w1l + (size_t)l * 4 * EMB * EMB,
            fc1_b + (size_t)l * 4 * EMB, nullptr, nullptr, f1hi, f1lo, 4 * EMB, EMB);

        // x = x + f1 @ fc2_w + fc2_b   (N=768, K=3072 -> 6 n-tiles)
        tc_gemm<2, 0><<<32 * 6, 128, GEMM_SMEM>>>(
            f1hi, f1lo, w2h + (size_t)l * 4 * EMB * EMB, w2l + (size_t)l * 4 * EMB * EMB,
            fc2_b + (size_t)l * EMB, gx, gx, nullptr, nullptr, EMB, 4 * EMB);
    }

    ln_kernel<<<MROW, 256>>>(gx, lnf_w, lnf_b, hhi, hlo);

    // logits = h @ wte^T  (N=50257 -> 393 n-tiles, ragged)
    tc_gemm<0, 1><<<32 * 393, 128, GEMM_SMEM>>>(
        hhi, hlo, wth, wtl, nullptr, nullptr, out, nullptr, nullptr, VOCAB, EMB);
}

// round 10
// speedup vs baseline: 2.2030x; 1.1507x over previous
#include <cuda_runtime.h>
#include <cuda_fp16.h>
#include <math.h>
#include <stdint.h>

// GPT-2 small config
#define BATCH 4
#define TLEN  1024
#define EMB   768
#define NLAYER 12
#define VOCAB 50257
#define NHEAD 12
#define HEADD 64
#define MROW  (BATCH * TLEN)   // 4096

// ---------------- scratch (device globals; no allocation allowed) ----------------
__device__ float g_x[MROW * EMB];        // residual stream (fp32)
__device__ float g_qkv[MROW * 3 * EMB];  // qkv projection (fp32, attn consumer)

// fp16 activations (A operands, single precision-level)
__device__ __half g_h[MROW * EMB];
__device__ __half g_y[MROW * EMB];
__device__ __half g_f1[MROW * 4 * EMB];

// split-fp16 weights, stored [N][K] (K-major rows) for ldmatrix col access
__device__ __half g_wqkv_hi[NLAYER * 3 * EMB * EMB], g_wqkv_lo[NLAYER * 3 * EMB * EMB];
__device__ __half g_wproj_hi[NLAYER * EMB * EMB],    g_wproj_lo[NLAYER * EMB * EMB];
__device__ __half g_wf1_hi[NLAYER * 4 * EMB * EMB],  g_wf1_lo[NLAYER * 4 * EMB * EMB];
__device__ __half g_wf2_hi[NLAYER * 4 * EMB * EMB],  g_wf2_lo[NLAYER * 4 * EMB * EMB];
__device__ __half g_wte_hi[VOCAB * EMB],             g_wte_lo[VOCAB * EMB];

// ======================= helpers =======================
__device__ __forceinline__ uint32_t smem_u32(const void* p) {
    uint32_t a;
    asm("{ .reg .u64 t; cvta.to.shared.u64 t, %1; cvt.u32.u64 %0, t; }"
        : "=r"(a) : "l"(p));
    return a;
}
__device__ __forceinline__ void ldsm_x4(uint32_t addr, uint32_t* r) {
    asm volatile("ldmatrix.sync.aligned.m8n8.x4.shared.b16 {%0,%1,%2,%3}, [%4];"
                 : "=r"(r[0]), "=r"(r[1]), "=r"(r[2]), "=r"(r[3]) : "r"(addr));
}
__device__ __forceinline__ void ldsm_x2(uint32_t addr, uint32_t* r) {
    asm volatile("ldmatrix.sync.aligned.m8n8.x2.shared.b16 {%0,%1}, [%2];"
                 : "=r"(r[0]), "=r"(r[1]) : "r"(addr));
}
__device__ __forceinline__ void mma_fp16(float* d, const uint32_t* a, const uint32_t* b) {
    asm volatile(
        "mma.sync.aligned.m16n8k16.row.col.f32.f16.f16.f32 "
        "{%0,%1,%2,%3}, {%4,%5,%6,%7}, {%8,%9}, {%0,%1,%2,%3};"
        : "+f"(d[0]), "+f"(d[1]), "+f"(d[2]), "+f"(d[3])
        : "r"(a[0]), "r"(a[1]), "r"(a[2]), "r"(a[3]), "r"(b[0]), "r"(b[1]));
}
__device__ __forceinline__ void cp16(uint32_t saddr, const void* g) {
    asm volatile("cp.async.cg.shared.global [%0], [%1], 16;" :: "r"(saddr), "l"(g));
}
__device__ __forceinline__ void cp16z(uint32_t saddr, const void* g, int ok) {
    int sz = ok ? 16 : 0;
    asm volatile("cp.async.cg.shared.global [%0], [%1], 16, %2;" :: "r"(saddr), "l"(g), "r"(sz));
}
#define CP_COMMIT() asm volatile("cp.async.commit_group;" ::: "memory")
#define CP_WAIT1()  asm volatile("cp.async.wait_group 1;" ::: "memory")

__device__ __forceinline__ float gelu_f(float x) {
    return 0.5f * x * (1.0f + erff(x * 0.7071067811865476f));
}

// ======================= weight pre-split kernels =======================
// elementwise split (no transpose): wte [V][E] is already K-major per row
__global__ void split_kernel(const float* __restrict__ src,
                             __half* __restrict__ dhi,
                             __half* __restrict__ dlo, int n) {
    int i = blockIdx.x * blockDim.x + threadIdx.x;
    if (i >= n) return;
    float v = src[i];
    __half h = __float2half_rn(v);
    dhi[i] = h;
    dlo[i] = __float2half_rn(v - __half2float(h));
}

// transpose+split: src [K][N] fp32 -> dst [N][K] fp16 hi/lo. K,N multiples of 32.
__global__ void __launch_bounds__(256) splitT_kernel(const float* __restrict__ src,
                                                     __half* __restrict__ dhi,
                                                     __half* __restrict__ dlo,
                                                     int K, int N) {
    __shared__ float t[32][33];
    int tx = threadIdx.x & 31, ty = threadIdx.x >> 5;  // 32 x 8
    int bn = blockIdx.x * 32, bk = blockIdx.y * 32;
#pragma unroll
    for (int i = 0; i < 4; i++)
        t[ty + i * 8][tx] = src[(size_t)(bk + ty + i * 8) * N + bn + tx];
    __syncthreads();
#pragma unroll
    for (int i = 0; i < 4; i++) {
        int n = bn + ty + i * 8;
        int k = bk + tx;
        float v = t[tx][ty + i * 8];
        __half h = __float2half_rn(v);
        dhi[(size_t)n * K + k] = h;
        dlo[(size_t)n * K + k] = __float2half_rn(v - __half2float(h));
    }
}

// ======================= mma.sync fp16 2-product GEMM =======================
// C[4096, N] = A[M][K] @ (Bhi+Blo)[N][K]^T.  A single fp16, B split fp16.
// CTA tile 128x128, 4 warps (64x64), K-chunk 32, cp.async double buffer.
// EPI: 0=none(fp32 C), 1=+bias, 2=+bias+residual, 3=+bias,GELU -> fp16 out
// RAGGED: guard B rows / C cols against N (lm_head)
#define TCSTRIDE 80
#define REG_BH   10240
#define REG_BL   20480
#define STAGE_BYTES 30720
#define GEMM_SMEM (2 * STAGE_BYTES)

template <int EPI, int RAGGED>
__global__ void __launch_bounds__(128) tc_gemm(const __half* __restrict__ A,
                                               const __half* __restrict__ Bhi,
                                               const __half* __restrict__ Blo,
                                               const float* __restrict__ bias,
                                               const float* __restrict__ R,
                                               float* __restrict__ C,
                                               __half* __restrict__ Ch,
                                               int N, int K) {
    extern __shared__ char sm[];
    const uint32_t sbase = smem_u32(sm);
    const int tid = threadIdx.x;
    const int warp = tid >> 5, lane = tid & 31;

    // m-inner ordering: consecutive CTAs share the same B tile (L2 reuse)
    const int m0 = (blockIdx.x & 31) * 128;
    const int n0 = (blockIdx.x >> 5) * 128;

    const int warpM = (warp >> 1) * 64;
    const int warpN = (warp & 1) * 64;

    float acc[4][8][4];
#pragma unroll
    for (int i = 0; i < 4; i++)
#pragma unroll
        for (int j = 0; j < 8; j++)
#pragma unroll
            for (int c = 0; c < 4; c++) acc[i][j][c] = 0.f;

    // per-thread fill slots: 512 16B-chunks per region; row = id>>2, c = id&3
    int frow[4], fc[4];
#pragma unroll
    for (int u = 0; u < 4; u++) {
        int id = tid + (u << 7);
        frow[u] = id >> 2;
        fc[u] = id & 3;
    }

    const int NK = K >> 5;

    auto fill = [&](int s) {
        const uint32_t st = sbase + (s & 1) * STAGE_BYTES;
        const int k0 = s << 5;
#pragma unroll
        for (int u = 0; u < 4; u++) {
            int row = frow[u], c = fc[u];
            uint32_t so = st + row * TCSTRIDE + c * 16;
            cp16(so, A + (size_t)(m0 + row) * K + k0 + c * 8);
            int gn = n0 + row;
            if (RAGGED) {
                int ok = gn < N;
                int gnc = ok ? gn : 0;
                size_t gb = (size_t)gnc * K + k0 + c * 8;
                cp16z(so + REG_BH, Bhi + gb, ok);
                cp16z(so + REG_BL, Blo + gb, ok);
            } else {
                size_t gb = (size_t)gn * K + k0 + c * 8;
                cp16(so + REG_BH, Bhi + gb);
                cp16(so + REG_BL, Blo + gb);
            }
        }
    };

    fill(0); CP_COMMIT();
    fill(1); CP_COMMIT();

    const uint32_t aoff = (uint32_t)((warpM + (lane & 15)) * TCSTRIDE + ((lane >> 4) * 8) * 2);
    const uint32_t boff = (uint32_t)((warpN + (lane & 7)) * TCSTRIDE + (((lane >> 3) & 1) * 8) * 2);

    for (int kt = 0; kt < NK; kt++) {
        CP_WAIT1();
        __syncthreads();
        const uint32_t st = sbase + (kt & 1) * STAGE_BYTES;

#pragma unroll
        for (int ks = 0; ks < 2; ks++) {
            uint32_t af[4][4];
#pragma unroll
            for (int mt = 0; mt < 4; mt++)
                ldsm_x4(st + aoff + mt * (16 * TCSTRIDE) + (ks * 32), af[mt]);
#pragma unroll
            for (int nh = 0; nh < 2; nh++) {
                uint32_t bhi[4][2], blo[4][2];
#pragma unroll
                for (int j = 0; j < 4; j++) {
                    uint32_t bd = st + REG_BH + boff + (nh * 4 + j) * (8 * TCSTRIDE) + (ks * 32);
                    ldsm_x2(bd, bhi[j]);
                    ldsm_x2(bd + (REG_BL - REG_BH), blo[j]);
                }
#pragma unroll
                for (int mt = 0; mt < 4; mt++)
#pragma unroll
                    for (int j = 0; j < 4; j++)
                        mma_fp16(acc[mt][nh * 4 + j], af[mt], bhi[j]);
#pragma unroll
                for (int mt = 0; mt < 4; mt++)
#pragma unroll
                    for (int j = 0; j < 4; j++)
                        mma_fp16(acc[mt][nh * 4 + j], af[mt], blo[j]);
            }
        }
        __syncthreads();
        if (kt + 2 < NK) fill(kt + 2);
        CP_COMMIT();
    }

    // ---- epilogue ----
    const int g = lane >> 2, t4 = lane & 3;
#pragma unroll
    for (int mt = 0; mt < 4; mt++) {
#pragma unroll
        for (int nt = 0; nt < 8; nt++) {
            int col = n0 + warpN + nt * 8 + 2 * t4;
            int row0 = m0 + warpM + mt * 16 + g;
#pragma unroll
            for (int h = 0; h < 2; h++) {
                int rowg = row0 + h * 8;
                float v0 = acc[mt][nt][2 * h];
                float v1 = acc[mt][nt][2 * h + 1];
                if (RAGGED) {
                    if (col < N) {
                        if (EPI >= 1) v0 += bias[col];
                        C[(size_t)rowg * N + col] = v0;
                    }
                    if (col + 1 < N) {
                        if (EPI >= 1) v1 += bias[col + 1];
                        C[(size_t)rowg * N + col + 1] = v1;
                    }
                } else if (EPI == 3) {
                    v0 = gelu_f(v0 + bias[col]);
                    v1 = gelu_f(v1 + bias[col + 1]);
                    *(__half2*)&Ch[(size_t)rowg * N + col] =
                        __floats2half2_rn(v0, v1);
                } else {
                    if (EPI >= 1) { v0 += bias[col]; v1 += bias[col + 1]; }
                    if (EPI == 2) {
                        v0 += R[(size_t)rowg * N + col];
                        v1 += R[(size_t)rowg * N + col + 1];
                    }
                    float2 o = make_float2(v0, v1);
                    *(float2*)&C[(size_t)rowg * N + col] = o;
                }
            }
        }
    }
}

// ---------------- embedding: x = wte[idx] + wpe[t] ----------------
__global__ void embed_kernel(const int* __restrict__ idx,
                             const float* __restrict__ wte,
                             const float* __restrict__ wpe,
                             float* __restrict__ x) {
    int i = blockIdx.x * blockDim.x + threadIdx.x;
    if (i >= MROW * EMB) return;
    int row = i / EMB;
    int e = i - row * EMB;
    int t = row % TLEN;
    x[i] = wte[(size_t)idx[row] * EMB + e] + wpe[(size_t)t * EMB + e];
}

// ---------------- layernorm: fp32 in, fp16 out ----------------
__global__ void __launch_bounds__(256) ln_kernel(const float* __restrict__ x,
                                                 const float* __restrict__ w,
                                                 const float* __restrict__ b,
                                                 __half* __restrict__ o16) {
    __shared__ float red[8];
    __shared__ float s_mean, s_var;
    int row = blockIdx.x;
    int tid = threadIdx.x;
    int warp = tid >> 5, lane = tid & 31;
    const float* xr = x + (size_t)row * EMB;

    float v0 = xr[tid], v1 = xr[tid + 256], v2 = xr[tid + 512];
    float s = v0 + v1 + v2;
#pragma unroll
    for (int o = 16; o; o >>= 1) s += __shfl_xor_sync(0xffffffffu, s, o);
    if (lane == 0) red[warp] = s;
    __syncthreads();
    if (tid == 0) {
        float t = 0.f;
#pragma unroll
        for (int i = 0; i < 8; i++) t += red[i];
        s_mean = t * (1.0f / EMB);
    }
    __syncthreads();
    float m = s_mean;
    float d0 = v0 - m, d1 = v1 - m, d2 = v2 - m;
    float q = d0 * d0 + d1 * d1 + d2 * d2;
#pragma unroll
    for (int o = 16; o; o >>= 1) q += __shfl_xor_sync(0xffffffffu, q, o);
    if (lane == 0) red[warp] = q;
    __syncthreads();
    if (tid == 0) {
        float t = 0.f;
#pragma unroll
        for (int i = 0; i < 8; i++) t += red[i];
        s_var = t * (1.0f / EMB);
    }
    __syncthreads();
    float r = rsqrtf(s_var + 1e-5f);
    size_t base = (size_t)row * EMB;
#pragma unroll
    for (int u = 0; u < 3; u++) {
        int e = tid + u * 256;
        float d = (u == 0 ? d0 : (u == 1 ? d1 : d2));
        o16[base + e] = __float2half_rn(d * r * w[e] + b[e]);
    }
}

// ---------------- attention: warp-per-query online softmax, fp16 out ----------------
__global__ void __launch_bounds__(256) attn_kernel(const float* __restrict__ qkv,
                                                   __half* __restrict__ y16) {
    __shared__ float Ks[64][64];
    __shared__ float Vs[64][64];
    int bh = blockIdx.x;
    int b = bh / NHEAD, h = bh % NHEAD;
    int q0 = blockIdx.y * 8;
    int warp = threadIdx.x >> 5, lane = threadIdx.x & 31;
    int q = q0 + warp;

    size_t qbase = ((size_t)(b * TLEN + q)) * (3 * EMB) + h * HEADD;
    float2 qv = *(const float2*)&qkv[qbase + 2 * lane];

    float m = -1e30f, lsum = 0.f, ax = 0.f, ay = 0.f;
    int nch = q0 / 64 + 1;

    for (int c = 0; c < nch; c++) {
        int kb = c * 64;
        for (int i = threadIdx.x; i < 64 * 64; i += 256) {
            int kk = i >> 6, d = i & 63;
            size_t base = ((size_t)(b * TLEN + kb + kk)) * (3 * EMB) + h * HEADD + d;
            Ks[kk][d] = qkv[base + EMB];
            Vs[kk][d] = qkv[base + 2 * EMB];
        }
        __syncthreads();

        int jmax = q - kb;
        if (jmax > 63) jmax = 63;
        for (int j = 0; j <= jmax; j++) {
            float s = qv.x * Ks[j][2 * lane] + qv.y * Ks[j][2 * lane + 1];
#pragma unroll
            for (int o = 16; o; o >>= 1) s += __shfl_xor_sync(0xffffffffu, s, o);
            s *= 0.125f;
            float mn = fmaxf(m, s);
            float corr = __expf(m - mn);
            float p = __expf(s - mn);
            ax = ax * corr + p * Vs[j][2 * lane];
            ay = ay * corr + p * Vs[j][2 * lane + 1];
            lsum = lsum * corr + p;
            m = mn;
        }
        __syncthreads();
    }

    float inv = 1.0f / lsum;
    size_t o = ((size_t)(b * TLEN + q)) * EMB + h * HEADD + 2 * lane;
    *(__half2*)&y16[o] = __floats2half2_rn(ax * inv, ay * inv);
}

// ---------------- host launch ----------------
extern "C" void kernel_launch(void* const* d_in, const int* in_sizes, int n_in,
                              void* d_out, int out_size) {
    (void)in_sizes; (void)n_in; (void)out_size;
    const int*   x_idx  = (const int*)d_in[0];
    const float* wte    = (const float*)d_in[1];
    const float* wpe    = (const float*)d_in[2];
    const float* ln1_w  = (const float*)d_in[3];
    const float* ln1_b  = (const float*)d_in[4];
    const float* attn_w = (const float*)d_in[5];
    const float* attn_b = (const float*)d_in[6];
    const float* proj_w = (const float*)d_in[7];
    const float* proj_b = (const float*)d_in[8];
    const float* ln2_w  = (const float*)d_in[9];
    const float* ln2_b  = (const float*)d_in[10];
    const float* fc1_w  = (const float*)d_in[11];
    const float* fc1_b  = (const float*)d_in[12];
    const float* fc2_w  = (const float*)d_in[13];
    const float* fc2_b  = (const float*)d_in[14];
    const float* lnf_w  = (const float*)d_in[15];
    const float* lnf_b  = (const float*)d_in[16];
    float* out = (float*)d_out;

    float *gx, *gqkv;
    __half *gh, *gy, *gf1;
    __half *wqh, *wql, *wph, *wpl, *w1h, *w1l, *w2h, *w2l, *wth, *wtl;
    cudaGetSymbolAddress((void**)&gx,   g_x);
    cudaGetSymbolAddress((void**)&gqkv, g_qkv);
    cudaGetSymbolAddress((void**)&gh,   g_h);
    cudaGetSymbolAddress((void**)&gy,   g_y);
    cudaGetSymbolAddress((void**)&gf1,  g_f1);
    cudaGetSymbolAddress((void**)&wqh,  g_wqkv_hi);
    cudaGetSymbolAddress((void**)&wql,  g_wqkv_lo);
    cudaGetSymbolAddress((void**)&wph,  g_wproj_hi);
    cudaGetSymbolAddress((void**)&wpl,  g_wproj_lo);
    cudaGetSymbolAddress((void**)&w1h,  g_wf1_hi);
    cudaGetSymbolAddress((void**)&w1l,  g_wf1_lo);
    cudaGetSymbolAddress((void**)&w2h,  g_wf2_hi);
    cudaGetSymbolAddress((void**)&w2l,  g_wf2_lo);
    cudaGetSymbolAddress((void**)&wth,  g_wte_hi);
    cudaGetSymbolAddress((void**)&wtl,  g_wte_lo);

    cudaFuncSetAttribute(tc_gemm<1, 0>, cudaFuncAttributeMaxDynamicSharedMemorySize, GEMM_SMEM);
    cudaFuncSetAttribute(tc_gemm<2, 0>, cudaFuncAttributeMaxDynamicSharedMemorySize, GEMM_SMEM);
    cudaFuncSetAttribute(tc_gemm<3, 0>, cudaFuncAttributeMaxDynamicSharedMemorySize, GEMM_SMEM);
    cudaFuncSetAttribute(tc_gemm<0, 1>, cudaFuncAttributeMaxDynamicSharedMemorySize, GEMM_SMEM);

    // ---- pre-split weights ----
    split_kernel<<<(VOCAB * EMB + 255) / 256, 256>>>(wte, wth, wtl, VOCAB * EMB);
    for (int l = 0; l < NLAYER; l++) {
        splitT_kernel<<<dim3(3 * EMB / 32, EMB / 32), 256>>>(
            attn_w + (size_t)l * EMB * 3 * EMB,
            wqh + (size_t)l * 3 * EMB * EMB, wql + (size_t)l * 3 * EMB * EMB, EMB, 3 * EMB);
        splitT_kernel<<<dim3(EMB / 32, EMB / 32), 256>>>(
            proj_w + (size_t)l * EMB * EMB,
            wph + (size_t)l * EMB * EMB, wpl + (size_t)l * EMB * EMB, EMB, EMB);
        splitT_kernel<<<dim3(4 * EMB / 32, EMB / 32), 256>>>(
            fc1_w + (size_t)l * EMB * 4 * EMB,
            w1h + (size_t)l * 4 * EMB * EMB, w1l + (size_t)l * 4 * EMB * EMB, EMB, 4 * EMB);
        splitT_kernel<<<dim3(EMB / 32, 4 * EMB / 32), 256>>>(
            fc2_w + (size_t)l * 4 * EMB * EMB,
            w2h + (size_t)l * 4 * EMB * EMB, w2l + (size_t)l * 4 * EMB * EMB, 4 * EMB, EMB);
    }

    embed_kernel<<<(MROW * EMB + 255) / 256, 256>>>(x_idx, wte, wpe, gx);

    for (int l = 0; l < NLAYER; l++) {
        ln_kernel<<<MROW, 256>>>(gx, ln1_w + (size_t)l * EMB, ln1_b + (size_t)l * EMB, gh);

        // qkv = h @ attn_w + attn_b    (N=2304 -> 18 n-tiles)
        tc_gemm<1, 0><<<32 * 18, 128, GEMM_SMEM>>>(
            gh, wqh + (size_t)l * 3 * EMB * EMB, wql + (size_t)l * 3 * EMB * EMB,
            attn_b + (size_t)l * 3 * EMB, nullptr, gqkv, nullptr, 3 * EMB, EMB);

        attn_kernel<<<dim3(BATCH * NHEAD, TLEN / 8), 256>>>(gqkv, gy);

        // x = x + y @ proj_w + proj_b  (N=768 -> 6 n-tiles)
        tc_gemm<2, 0><<<32 * 6, 128, GEMM_SMEM>>>(
            gy, wph + (size_t)l * EMB * EMB, wpl + (size_t)l * EMB * EMB,
            proj_b + (size_t)l * EMB, gx, gx, nullptr, EMB, EMB);

        ln_kernel<<<MROW, 256>>>(gx, ln2_w + (size_t)l * EMB, ln2_b + (size_t)l * EMB, gh);

        // f1 = gelu(h @ fc1_w + fc1_b) -> fp16  (N=3072 -> 24 n-tiles)
        tc_gemm<3, 0><<<32 * 24, 128, GEMM_SMEM>>>(
            gh, w1h + (size_t)l * 4 * EMB * EMB, w1l + (size_t)l * 4 * EMB * EMB,
            fc1_b + (size_t)l * 4 * EMB, nullptr, nullptr, gf1, 4 * EMB, EMB);

        // x = x + f1 @ fc2_w + fc2_b   (N=768, K=3072 -> 6 n-tiles)
        tc_gemm<2, 0><<<32 * 6, 128, GEMM_SMEM>>>(
            gf1, w2h + (size_t)l * 4 * EMB * EMB, w2l + (size_t)l * 4 * EMB * EMB,
            fc2_b + (size_t)l * EMB, gx, gx, nullptr, EMB, 4 * EMB);
    }

    ln_kernel<<<MROW, 256>>>(gx, lnf_w, lnf_b, gh);

    // logits = h @ wte^T  (N=50257 -> 393 n-tiles, ragged)
    tc_gemm<0, 1><<<32 * 393, 128, GEMM_SMEM>>>(
        gh, wth, wtl, nullptr, nullptr, out, nullptr, VOCAB, EMB);
}

// round 11
// speedup vs baseline: 2.6189x; 1.1888x over previous
#include <cuda_runtime.h>
#include <cuda_fp16.h>
#include <math.h>
#include <stdint.h>

// GPT-2 small config
#define BATCH 4
#define TLEN  1024
#define EMB   768
#define NLAYER 12
#define VOCAB 50257
#define NHEAD 12
#define HEADD 64
#define MROW  (BATCH * TLEN)   // 4096

// ---------------- scratch (device globals; no allocation allowed) ----------------
__device__ float g_x[MROW * EMB];        // residual stream (fp32)
__device__ float g_qkv[MROW * 3 * EMB];  // qkv projection (fp32, attn consumer)

// fp16 activations
__device__ __half g_h[MROW * EMB];
__device__ __half g_y[MROW * EMB];
__device__ __half g_f1[MROW * 4 * EMB];

// fp16 weights, stored [N][K] (K-major rows) for ldmatrix col access
__device__ __half g_wqkv[NLAYER * 3 * EMB * EMB];
__device__ __half g_wproj[NLAYER * EMB * EMB];
__device__ __half g_wf1[NLAYER * 4 * EMB * EMB];
__device__ __half g_wf2[NLAYER * 4 * EMB * EMB];
__device__ __half g_wte16[VOCAB * EMB];

// ======================= helpers =======================
__device__ __forceinline__ uint32_t smem_u32(const void* p) {
    uint32_t a;
    asm("{ .reg .u64 t; cvta.to.shared.u64 t, %1; cvt.u32.u64 %0, t; }"
        : "=r"(a) : "l"(p));
    return a;
}
__device__ __forceinline__ void ldsm_x4(uint32_t addr, uint32_t* r) {
    asm volatile("ldmatrix.sync.aligned.m8n8.x4.shared.b16 {%0,%1,%2,%3}, [%4];"
                 : "=r"(r[0]), "=r"(r[1]), "=r"(r[2]), "=r"(r[3]) : "r"(addr));
}
__device__ __forceinline__ void ldsm_x2(uint32_t addr, uint32_t* r) {
    asm volatile("ldmatrix.sync.aligned.m8n8.x2.shared.b16 {%0,%1}, [%2];"
                 : "=r"(r[0]), "=r"(r[1]) : "r"(addr));
}
__device__ __forceinline__ void mma_fp16(float* d, const uint32_t* a, const uint32_t* b) {
    asm volatile(
        "mma.sync.aligned.m16n8k16.row.col.f32.f16.f16.f32 "
        "{%0,%1,%2,%3}, {%4,%5,%6,%7}, {%8,%9}, {%0,%1,%2,%3};"
        : "+f"(d[0]), "+f"(d[1]), "+f"(d[2]), "+f"(d[3])
        : "r"(a[0]), "r"(a[1]), "r"(a[2]), "r"(a[3]), "r"(b[0]), "r"(b[1]));
}
__device__ __forceinline__ void cp16(uint32_t saddr, const void* g) {
    asm volatile("cp.async.cg.shared.global [%0], [%1], 16;" :: "r"(saddr), "l"(g));
}
__device__ __forceinline__ void cp16z(uint32_t saddr, const void* g, int ok) {
    int sz = ok ? 16 : 0;
    asm volatile("cp.async.cg.shared.global [%0], [%1], 16, %2;" :: "r"(saddr), "l"(g), "r"(sz));
}
#define CP_COMMIT() asm volatile("cp.async.commit_group;" ::: "memory")
#define CP_WAIT1()  asm volatile("cp.async.wait_group 1;" ::: "memory")

__device__ __forceinline__ float gelu_f(float x) {
    return 0.5f * x * (1.0f + erff(x * 0.7071067811865476f));
}

// ======================= weight convert kernels =======================
__global__ void cvt_kernel(const float* __restrict__ src,
                           __half* __restrict__ dst, int n) {
    int i = blockIdx.x * blockDim.x + threadIdx.x;
    if (i >= n) return;
    dst[i] = __float2half_rn(src[i]);
}

// transpose+convert for TWO weight families in one launch.
// blockIdx.z in [0, 24): z<12 -> family A layer z; else family B layer z-12.
// Each: src [K][N] fp32 (per-layer stride K*N) -> dst [N][K] fp16.
__global__ void __launch_bounds__(256) cvtT2_kernel(
    const float* __restrict__ srcA, __half* __restrict__ dstA, int KA, int NA,
    const float* __restrict__ srcB, __half* __restrict__ dstB, int KB, int NB) {
    __shared__ float t[32][33];
    int z = blockIdx.z;
    const float* src;  __half* dst;  int K, N;
    if (z < NLAYER) {
        src = srcA + (size_t)z * KA * NA;  dst = dstA + (size_t)z * KA * NA;
        K = KA;  N = NA;
    } else {
        src = srcB + (size_t)(z - NLAYER) * KB * NB;  dst = dstB + (size_t)(z - NLAYER) * KB * NB;
        K = KB;  N = NB;
    }
    int bn = blockIdx.x * 32, bk = blockIdx.y * 32;
    if (bn >= N || bk >= K) return;
    int tx = threadIdx.x & 31, ty = threadIdx.x >> 5;  // 32 x 8
#pragma unroll
    for (int i = 0; i < 4; i++)
        t[ty + i * 8][tx] = src[(size_t)(bk + ty + i * 8) * N + bn + tx];
    __syncthreads();
#pragma unroll
    for (int i = 0; i < 4; i++) {
        int n = bn + ty + i * 8;
        int k = bk + tx;
        dst[(size_t)n * K + k] = __float2half_rn(t[tx][ty + i * 8]);
    }
}

// ======================= mma.sync fp16 GEMM (1 product) =======================
// C[4096, N] = A[M][K] @ B[N][K]^T, both fp16.
// CTA tile 128x128, 4 warps (64x64), K-chunk 32, cp.async double buffer.
// EPI: 0=none(fp32 C), 1=+bias, 2=+bias+residual, 3=+bias,GELU -> fp16 out
// RAGGED: guard B rows / C cols against N (lm_head)
#define TCSTRIDE 80
#define REG_B    10240
#define STAGE_BYTES 20480
#define GEMM_SMEM (2 * STAGE_BYTES)

template <int EPI, int RAGGED>
__global__ void __launch_bounds__(128) tc_gemm(const __half* __restrict__ A,
                                               const __half* __restrict__ B,
                                               const float* __restrict__ bias,
                                               const float* __restrict__ R,
                                               float* __restrict__ C,
                                               __half* __restrict__ Ch,
                                               int N, int K) {
    extern __shared__ char sm[];
    const uint32_t sbase = smem_u32(sm);
    const int tid = threadIdx.x;
    const int warp = tid >> 5, lane = tid & 31;

    // m-inner ordering: consecutive CTAs share the same B tile (L2 reuse)
    const int m0 = (blockIdx.x & 31) * 128;
    const int n0 = (blockIdx.x >> 5) * 128;

    const int warpM = (warp >> 1) * 64;
    const int warpN = (warp & 1) * 64;

    float acc[4][8][4];
#pragma unroll
    for (int i = 0; i < 4; i++)
#pragma unroll
        for (int j = 0; j < 8; j++)
#pragma unroll
            for (int c = 0; c < 4; c++) acc[i][j][c] = 0.f;

    int frow[4], fc[4];
#pragma unroll
    for (int u = 0; u < 4; u++) {
        int id = tid + (u << 7);
        frow[u] = id >> 2;
        fc[u] = id & 3;
    }

    const int NK = K >> 5;

    auto fill = [&](int s) {
        const uint32_t st = sbase + (s & 1) * STAGE_BYTES;
        const int k0 = s << 5;
#pragma unroll
        for (int u = 0; u < 4; u++) {
            int row = frow[u], c = fc[u];
            uint32_t so = st + row * TCSTRIDE + c * 16;
            cp16(so, A + (size_t)(m0 + row) * K + k0 + c * 8);
            int gn = n0 + row;
            if (RAGGED) {
                int ok = gn < N;
                int gnc = ok ? gn : 0;
                cp16z(so + REG_B, B + (size_t)gnc * K + k0 + c * 8, ok);
            } else {
                cp16(so + REG_B, B + (size_t)gn * K + k0 + c * 8);
            }
        }
    };

    fill(0); CP_COMMIT();
    fill(1); CP_COMMIT();

    const uint32_t aoff = (uint32_t)((warpM + (lane & 15)) * TCSTRIDE + ((lane >> 4) * 8) * 2);
    const uint32_t boff = (uint32_t)((warpN + (lane & 7)) * TCSTRIDE + (((lane >> 3) & 1) * 8) * 2);

    for (int kt = 0; kt < NK; kt++) {
        CP_WAIT1();
        __syncthreads();
        const uint32_t st = sbase + (kt & 1) * STAGE_BYTES;

#pragma unroll
        for (int ks = 0; ks < 2; ks++) {
            uint32_t af[4][4];
#pragma unroll
            for (int mt = 0; mt < 4; mt++)
                ldsm_x4(st + aoff + mt * (16 * TCSTRIDE) + (ks * 32), af[mt]);
#pragma unroll
            for (int nh = 0; nh < 2; nh++) {
                uint32_t bf[4][2];
#pragma unroll
                for (int j = 0; j < 4; j++)
                    ldsm_x2(st + REG_B + boff + (nh * 4 + j) * (8 * TCSTRIDE) + (ks * 32), bf[j]);
#pragma unroll
                for (int mt = 0; mt < 4; mt++)
#pragma unroll
                    for (int j = 0; j < 4; j++)
                        mma_fp16(acc[mt][nh * 4 + j], af[mt], bf[j]);
            }
        }
        __syncthreads();
        if (kt + 2 < NK) fill(kt + 2);
        CP_COMMIT();
    }

    // ---- epilogue ----
    const int g = lane >> 2, t4 = lane & 3;
#pragma unroll
    for (int mt = 0; mt < 4; mt++) {
#pragma unroll
        for (int nt = 0; nt < 8; nt++) {
            int col = n0 + warpN + nt * 8 + 2 * t4;
            int row0 = m0 + warpM + mt * 16 + g;
#pragma unroll
            for (int h = 0; h < 2; h++) {
                int rowg = row0 + h * 8;
                float v0 = acc[mt][nt][2 * h];
                float v1 = acc[mt][nt][2 * h + 1];
                if (RAGGED) {
                    if (col < N) {
                        if (EPI >= 1) v0 += bias[col];
                        C[(size_t)rowg * N + col] = v0;
                    }
                    if (col + 1 < N) {
                        if (EPI >= 1) v1 += bias[col + 1];
                        C[(size_t)rowg * N + col + 1] = v1;
                    }
                } else if (EPI == 3) {
                    v0 = gelu_f(v0 + bias[col]);
                    v1 = gelu_f(v1 + bias[col + 1]);
                    *(__half2*)&Ch[(size_t)rowg * N + col] = __floats2half2_rn(v0, v1);
                } else {
                    if (EPI >= 1) { v0 += bias[col]; v1 += bias[col + 1]; }
                    if (EPI == 2) {
                        v0 += R[(size_t)rowg * N + col];
                        v1 += R[(size_t)rowg * N + col + 1];
                    }
                    float2 o = make_float2(v0, v1);
                    *(float2*)&C[(size_t)rowg * N + col] = o;
                }
            }
        }
    }
}

// ---------------- embedding: x = wte[idx] + wpe[t] ----------------
__global__ void embed_kernel(const int* __restrict__ idx,
                             const float* __restrict__ wte,
                             const float* __restrict__ wpe,
                             float* __restrict__ x) {
    int i = blockIdx.x * blockDim.x + threadIdx.x;
    if (i >= MROW * EMB) return;
    int row = i / EMB;
    int e = i - row * EMB;
    int t = row % TLEN;
    x[i] = wte[(size_t)idx[row] * EMB + e] + wpe[(size_t)t * EMB + e];
}

// ---------------- layernorm: fp32 in, fp16 out ----------------
__global__ void __launch_bounds__(256) ln_kernel(const float* __restrict__ x,
                                                 const float* __restrict__ w,
                                                 const float* __restrict__ b,
                                                 __half* __restrict__ o16) {
    __shared__ float red[8];
    __shared__ float s_mean, s_var;
    int row = blockIdx.x;
    int tid = threadIdx.x;
    int warp = tid >> 5, lane = tid & 31;
    const float* xr = x + (size_t)row * EMB;

    float v0 = xr[tid], v1 = xr[tid + 256], v2 = xr[tid + 512];
    float s = v0 + v1 + v2;
#pragma unroll
    for (int o = 16; o; o >>= 1) s += __shfl_xor_sync(0xffffffffu, s, o);
    if (lane == 0) red[warp] = s;
    __syncthreads();
    if (tid == 0) {
        float t = 0.f;
#pragma unroll
        for (int i = 0; i < 8; i++) t += red[i];
        s_mean = t * (1.0f / EMB);
    }
    __syncthreads();
    float m = s_mean;
    float d0 = v0 - m, d1 = v1 - m, d2 = v2 - m;
    float q = d0 * d0 + d1 * d1 + d2 * d2;
#pragma unroll
    for (int o = 16; o; o >>= 1) q += __shfl_xor_sync(0xffffffffu, q, o);
    if (lane == 0) red[warp] = q;
    __syncthreads();
    if (tid == 0) {
        float t = 0.f;
#pragma unroll
        for (int i = 0; i < 8; i++) t += red[i];
        s_var = t * (1.0f / EMB);
    }
    __syncthreads();
    float r = rsqrtf(s_var + 1e-5f);
    size_t base = (size_t)row * EMB;
#pragma unroll
    for (int u = 0; u < 3; u++) {
        int e = tid + u * 256;
        float d = (u == 0 ? d0 : (u == 1 ? d1 : d2));
        o16[base + e] = __float2half_rn(d * r * w[e] + b[e]);
    }
}

// ---------------- attention: warp-per-query online softmax, fp16 out ----------------
__global__ void __launch_bounds__(256) attn_kernel(const float* __restrict__ qkv,
                                                   __half* __restrict__ y16) {
    __shared__ float Ks[64][64];
    __shared__ float Vs[64][64];
    int bh = blockIdx.x;
    int b = bh / NHEAD, h = bh % NHEAD;
    int q0 = blockIdx.y * 8;
    int warp = threadIdx.x >> 5, lane = threadIdx.x & 31;
    int q = q0 + warp;

    size_t qbase = ((size_t)(b * TLEN + q)) * (3 * EMB) + h * HEADD;
    float2 qv = *(const float2*)&qkv[qbase + 2 * lane];

    float m = -1e30f, lsum = 0.f, ax = 0.f, ay = 0.f;
    int nch = q0 / 64 + 1;

    for (int c = 0; c < nch; c++) {
        int kb = c * 64;
        for (int i = threadIdx.x; i < 64 * 64; i += 256) {
            int kk = i >> 6, d = i & 63;
            size_t base = ((size_t)(b * TLEN + kb + kk)) * (3 * EMB) + h * HEADD + d;
            Ks[kk][d] = qkv[base + EMB];
            Vs[kk][d] = qkv[base + 2 * EMB];
        }
        __syncthreads();

        int jmax = q - kb;
        if (jmax > 63) jmax = 63;
        for (int j = 0; j <= jmax; j++) {
            float s = qv.x * Ks[j][2 * lane] + qv.y * Ks[j][2 * lane + 1];
#pragma unroll
            for (int o = 16; o; o >>= 1) s += __shfl_xor_sync(0xffffffffu, s, o);
            s *= 0.125f;
            float mn = fmaxf(m, s);
            float corr = __expf(m - mn);
            float p = __expf(s - mn);
            ax = ax * corr + p * Vs[j][2 * lane];
            ay = ay * corr + p * Vs[j][2 * lane + 1];
            lsum = lsum * corr + p;
            m = mn;
        }
        __syncthreads();
    }

    float inv = 1.0f / lsum;
    size_t o = ((size_t)(b * TLEN + q)) * EMB + h * HEADD + 2 * lane;
    *(__half2*)&y16[o] = __floats2half2_rn(ax * inv, ay * inv);
}

// ---------------- host launch ----------------
extern "C" void kernel_launch(void* const* d_in, const int* in_sizes, int n_in,
                              void* d_out, int out_size) {
    (void)in_sizes; (void)n_in; (void)out_size;
    const int*   x_idx  = (const int*)d_in[0];
    const float* wte    = (const float*)d_in[1];
    const float* wpe    = (const float*)d_in[2];
    const float* ln1_w  = (const float*)d_in[3];
    const float* ln1_b  = (const float*)d_in[4];
    const float* attn_w = (const float*)d_in[5];
    const float* attn_b = (const float*)d_in[6];
    const float* proj_w = (const float*)d_in[7];
    const float* proj_b = (const float*)d_in[8];
    const float* ln2_w  = (const float*)d_in[9];
    const float* ln2_b  = (const float*)d_in[10];
    const float* fc1_w  = (const float*)d_in[11];
    const float* fc1_b  = (const float*)d_in[12];
    const float* fc2_w  = (const float*)d_in[13];
    const float* fc2_b  = (const float*)d_in[14];
    const float* lnf_w  = (const float*)d_in[15];
    const float* lnf_b  = (const float*)d_in[16];
    float* out = (float*)d_out;

    float *gx, *gqkv;
    __half *gh, *gy, *gf1;
    __half *wq, *wp, *w1, *w2, *wt;
    cudaGetSymbolAddress((void**)&gx,   g_x);
    cudaGetSymbolAddress((void**)&gqkv, g_qkv);
    cudaGetSymbolAddress((void**)&gh,   g_h);
    cudaGetSymbolAddress((void**)&gy,   g_y);
    cudaGetSymbolAddress((void**)&gf1,  g_f1);
    cudaGetSymbolAddress((void**)&wq,   g_wqkv);
    cudaGetSymbolAddress((void**)&wp,   g_wproj);
    cudaGetSymbolAddress((void**)&w1,   g_wf1);
    cudaGetSymbolAddress((void**)&w2,   g_wf2);
    cudaGetSymbolAddress((void**)&wt,   g_wte16);

    cudaFuncSetAttribute(tc_gemm<1, 0>, cudaFuncAttributeMaxDynamicSharedMemorySize, GEMM_SMEM);
    cudaFuncSetAttribute(tc_gemm<2, 0>, cudaFuncAttributeMaxDynamicSharedMemorySize, GEMM_SMEM);
    cudaFuncSetAttribute(tc_gemm<3, 0>, cudaFuncAttributeMaxDynamicSharedMemorySize, GEMM_SMEM);
    cudaFuncSetAttribute(tc_gemm<0, 1>, cudaFuncAttributeMaxDynamicSharedMemorySize, GEMM_SMEM);

    // launch order puts the first qkv GEMM at launch #6 for the ncu capture (-s 5 -c 1)
    embed_kernel<<<(MROW * EMB + 255) / 256, 256>>>(x_idx, wte, wpe, gx);          // 1
    cvtT2_kernel<<<dim3(96, 24, 2 * NLAYER), 256>>>(                               // 2
        attn_w, wq, EMB, 3 * EMB, fc1_w, w1, EMB, 4 * EMB);
    cvtT2_kernel<<<dim3(24, 96, 2 * NLAYER), 256>>>(                               // 3
        proj_w, wp, EMB, EMB, fc2_w, w2, 4 * EMB, EMB);
    cvt_kernel<<<(VOCAB * EMB + 255) / 256, 256>>>(wte, wt, VOCAB * EMB);          // 4

    for (int l = 0; l < NLAYER; l++) {
        ln_kernel<<<MROW, 256>>>(gx, ln1_w + (size_t)l * EMB, ln1_b + (size_t)l * EMB, gh);  // 5

        // qkv = h @ attn_w + attn_b    (N=2304 -> 18 n-tiles)                     // 6 <- ncu
        tc_gemm<1, 0><<<32 * 18, 128, GEMM_SMEM>>>(
            gh, wq + (size_t)l * 3 * EMB * EMB,
            attn_b + (size_t)l * 3 * EMB, nullptr, gqkv, nullptr, 3 * EMB, EMB);

        attn_kernel<<<dim3(BATCH * NHEAD, TLEN / 8), 256>>>(gqkv, gy);

        // x = x + y @ proj_w + proj_b  (N=768 -> 6 n-tiles)
        tc_gemm<2, 0><<<32 * 6, 128, GEMM_SMEM>>>(
            gy, wp + (size_t)l * EMB * EMB,
            proj_b + (size_t)l * EMB, gx, gx, nullptr, EMB, EMB);

        ln_kernel<<<MROW, 256>>>(gx, ln2_w + (size_t)l * EMB, ln2_b + (size_t)l * EMB, gh);

        // f1 = gelu(h @ fc1_w + fc1_b) -> fp16  (N=3072 -> 24 n-tiles)
        tc_gemm<3, 0><<<32 * 24, 128, GEMM_SMEM>>>(
            gh, w1 + (size_t)l * 4 * EMB * EMB,
            fc1_b + (size_t)l * 4 * EMB, nullptr, nullptr, gf1, 4 * EMB, EMB);

        // x = x + f1 @ fc2_w + fc2_b   (N=768, K=3072 -> 6 n-tiles)
        tc_gemm<2, 0><<<32 * 6, 128, GEMM_SMEM>>>(
            gf1, w2 + (size_t)l * 4 * EMB * EMB,
            fc2_b + (size_t)l * EMB, gx, gx, nullptr, EMB, 4 * EMB);
    }

    ln_kernel<<<MROW, 256>>>(gx, lnf_w, lnf_b, gh);

    // logits = h @ wte^T  (N=50257 -> 393 n-tiles, ragged)
    tc_gemm<0, 1><<<32 * 393, 128, GEMM_SMEM>>>(
        gh, wt, nullptr, nullptr, out, nullptr, VOCAB, EMB);
}

// round 12
// speedup vs baseline: 8.5299x; 3.2570x over previous
#include <cuda_runtime.h>
#include <cuda_fp16.h>
#include <math.h>
#include <stdint.h>

// GPT-2 small config
#define BATCH 4
#define TLEN  1024
#define EMB   768
#define NLAYER 12
#define VOCAB 50257
#define NHEAD 12
#define HEADD 64
#define MROW  (BATCH * TLEN)   // 4096

// ---------------- scratch (device globals; no allocation allowed) ----------------
__device__ float g_x[MROW * EMB];        // residual stream (fp32)

// fp16 activations
__device__ __half g_h[MROW * EMB];
__device__ __half g_qkv16[MROW * 3 * EMB];
__device__ __half g_y[MROW * EMB];
__device__ __half g_f1[MROW * 4 * EMB];

// fp16 weights, stored [N][K] (K-major rows) for ldmatrix col access
__device__ __half g_wqkv[NLAYER * 3 * EMB * EMB];
__device__ __half g_wproj[NLAYER * EMB * EMB];
__device__ __half g_wf1[NLAYER * 4 * EMB * EMB];
__device__ __half g_wf2[NLAYER * 4 * EMB * EMB];
__device__ __half g_wte16[VOCAB * EMB];

// ======================= helpers =======================
__device__ __forceinline__ uint32_t smem_u32(const void* p) {
    uint32_t a;
    asm("{ .reg .u64 t; cvta.to.shared.u64 t, %1; cvt.u32.u64 %0, t; }"
        : "=r"(a) : "l"(p));
    return a;
}
__device__ __forceinline__ void ldsm_x4(uint32_t addr, uint32_t* r) {
    asm volatile("ldmatrix.sync.aligned.m8n8.x4.shared.b16 {%0,%1,%2,%3}, [%4];"
                 : "=r"(r[0]), "=r"(r[1]), "=r"(r[2]), "=r"(r[3]) : "r"(addr));
}
__device__ __forceinline__ void ldsm_x2(uint32_t addr, uint32_t* r) {
    asm volatile("ldmatrix.sync.aligned.m8n8.x2.shared.b16 {%0,%1}, [%2];"
                 : "=r"(r[0]), "=r"(r[1]) : "r"(addr));
}
__device__ __forceinline__ void ldsm_x2t(uint32_t addr, uint32_t* r) {
    asm volatile("ldmatrix.sync.aligned.m8n8.x2.trans.shared.b16 {%0,%1}, [%2];"
                 : "=r"(r[0]), "=r"(r[1]) : "r"(addr));
}
__device__ __forceinline__ void mma_fp16(float* d, const uint32_t* a, const uint32_t* b) {
    asm volatile(
        "mma.sync.aligned.m16n8k16.row.col.f32.f16.f16.f32 "
        "{%0,%1,%2,%3}, {%4,%5,%6,%7}, {%8,%9}, {%0,%1,%2,%3};"
        : "+f"(d[0]), "+f"(d[1]), "+f"(d[2]), "+f"(d[3])
        : "r"(a[0]), "r"(a[1]), "r"(a[2]), "r"(a[3]), "r"(b[0]), "r"(b[1]));
}
__device__ __forceinline__ void cp16(uint32_t saddr, const void* g) {
    asm volatile("cp.async.cg.shared.global [%0], [%1], 16;" :: "r"(saddr), "l"(g));
}
__device__ __forceinline__ void cp16z(uint32_t saddr, const void* g, int ok) {
    int sz = ok ? 16 : 0;
    asm volatile("cp.async.cg.shared.global [%0], [%1], 16, %2;" :: "r"(saddr), "l"(g), "r"(sz));
}
#define CP_COMMIT() asm volatile("cp.async.commit_group;" ::: "memory")
#define CP_WAIT1()  asm volatile("cp.async.wait_group 1;" ::: "memory")

__device__ __forceinline__ uint32_t packh2(float a, float b) {
    __half2 t = __floats2half2_rn(a, b);
    return reinterpret_cast<uint32_t&>(t);
}
__device__ __forceinline__ float gelu_f(float x) {
    return 0.5f * x * (1.0f + erff(x * 0.7071067811865476f));
}

// ======================= weight convert kernels =======================
__global__ void cvt_kernel(const float* __restrict__ src,
                           __half* __restrict__ dst, int n) {
    int i = blockIdx.x * blockDim.x + threadIdx.x;
    if (i >= n) return;
    dst[i] = __float2half_rn(src[i]);
}

// transpose+convert for TWO weight families in one launch.
__global__ void __launch_bounds__(256) cvtT2_kernel(
    const float* __restrict__ srcA, __half* __restrict__ dstA, int KA, int NA,
    const float* __restrict__ srcB, __half* __restrict__ dstB, int KB, int NB) {
    __shared__ float t[32][33];
    int z = blockIdx.z;
    const float* src;  __half* dst;  int K, N;
    if (z < NLAYER) {
        src = srcA + (size_t)z * KA * NA;  dst = dstA + (size_t)z * KA * NA;
        K = KA;  N = NA;
    } else {
        src = srcB + (size_t)(z - NLAYER) * KB * NB;  dst = dstB + (size_t)(z - NLAYER) * KB * NB;
        K = KB;  N = NB;
    }
    int bn = blockIdx.x * 32, bk = blockIdx.y * 32;
    if (bn >= N || bk >= K) return;
    int tx = threadIdx.x & 31, ty = threadIdx.x >> 5;
#pragma unroll
    for (int i = 0; i < 4; i++)
        t[ty + i * 8][tx] = src[(size_t)(bk + ty + i * 8) * N + bn + tx];
    __syncthreads();
#pragma unroll
    for (int i = 0; i < 4; i++) {
        int n = bn + ty + i * 8;
        int k = bk + tx;
        dst[(size_t)n * K + k] = __float2half_rn(t[tx][ty + i * 8]);
    }
}

// ======================= mma.sync fp16 GEMM =======================
// EPI: 0=none(fp32 C), 1=+bias(fp32), 2=+bias+residual(fp32),
//      3=+bias,GELU->fp16, 5=+bias->fp16
// RAGGED: guard B rows / C cols against N (lm_head)
#define TCSTRIDE 80
#define REG_B    10240
#define STAGE_BYTES 20480
#define GEMM_SMEM (2 * STAGE_BYTES)

template <int EPI, int RAGGED>
__global__ void __launch_bounds__(128) tc_gemm(const __half* __restrict__ A,
                                               const __half* __restrict__ B,
                                               const float* __restrict__ bias,
                                               const float* __restrict__ R,
                                               float* __restrict__ C,
                                               __half* __restrict__ Ch,
                                               int N, int K) {
    extern __shared__ char sm[];
    const uint32_t sbase = smem_u32(sm);
    const int tid = threadIdx.x;
    const int warp = tid >> 5, lane = tid & 31;

    const int m0 = (blockIdx.x & 31) * 128;
    const int n0 = (blockIdx.x >> 5) * 128;

    const int warpM = (warp >> 1) * 64;
    const int warpN = (warp & 1) * 64;

    float acc[4][8][4];
#pragma unroll
    for (int i = 0; i < 4; i++)
#pragma unroll
        for (int j = 0; j < 8; j++)
#pragma unroll
            for (int c = 0; c < 4; c++) acc[i][j][c] = 0.f;

    int frow[4], fcc[4];
#pragma unroll
    for (int u = 0; u < 4; u++) {
        int id = tid + (u << 7);
        frow[u] = id >> 2;
        fcc[u] = id & 3;
    }

    const int NK = K >> 5;

    auto fill = [&](int s) {
        const uint32_t st = sbase + (s & 1) * STAGE_BYTES;
        const int k0 = s << 5;
#pragma unroll
        for (int u = 0; u < 4; u++) {
            int row = frow[u], c = fcc[u];
            uint32_t so = st + row * TCSTRIDE + c * 16;
            cp16(so, A + (size_t)(m0 + row) * K + k0 + c * 8);
            int gn = n0 + row;
            if (RAGGED) {
                int ok = gn < N;
                int gnc = ok ? gn : 0;
                cp16z(so + REG_B, B + (size_t)gnc * K + k0 + c * 8, ok);
            } else {
                cp16(so + REG_B, B + (size_t)gn * K + k0 + c * 8);
            }
        }
    };

    fill(0); CP_COMMIT();
    fill(1); CP_COMMIT();

    const uint32_t aoff = (uint32_t)((warpM + (lane & 15)) * TCSTRIDE + ((lane >> 4) * 8) * 2);
    const uint32_t boff = (uint32_t)((warpN + (lane & 7)) * TCSTRIDE + (((lane >> 3) & 1) * 8) * 2);

    for (int kt = 0; kt < NK; kt++) {
        CP_WAIT1();
        __syncthreads();
        const uint32_t st = sbase + (kt & 1) * STAGE_BYTES;

#pragma unroll
        for (int ks = 0; ks < 2; ks++) {
            uint32_t af[4][4];
#pragma unroll
            for (int mt = 0; mt < 4; mt++)
                ldsm_x4(st + aoff + mt * (16 * TCSTRIDE) + (ks * 32), af[mt]);
#pragma unroll
            for (int nh = 0; nh < 2; nh++) {
                uint32_t bf[4][2];
#pragma unroll
                for (int j = 0; j < 4; j++)
                    ldsm_x2(st + REG_B + boff + (nh * 4 + j) * (8 * TCSTRIDE) + (ks * 32), bf[j]);
#pragma unroll
                for (int mt = 0; mt < 4; mt++)
#pragma unroll
                    for (int j = 0; j < 4; j++)
                        mma_fp16(acc[mt][nh * 4 + j], af[mt], bf[j]);
            }
        }
        __syncthreads();
        if (kt + 2 < NK) fill(kt + 2);
        CP_COMMIT();
    }

    // ---- epilogue ----
    const int g = lane >> 2, t4 = lane & 3;
#pragma unroll
    for (int mt = 0; mt < 4; mt++) {
#pragma unroll
        for (int nt = 0; nt < 8; nt++) {
            int col = n0 + warpN + nt * 8 + 2 * t4;
            int row0 = m0 + warpM + mt * 16 + g;
#pragma unroll
            for (int h = 0; h < 2; h++) {
                int rowg = row0 + h * 8;
                float v0 = acc[mt][nt][2 * h];
                float v1 = acc[mt][nt][2 * h + 1];
                if (RAGGED) {
                    if (col < N) {
                        if (EPI >= 1) v0 += bias[col];
                        C[(size_t)rowg * N + col] = v0;
                    }
                    if (col + 1 < N) {
                        if (EPI >= 1) v1 += bias[col + 1];
                        C[(size_t)rowg * N + col + 1] = v1;
                    }
                } else if (EPI == 3 || EPI == 5) {
                    v0 += bias[col]; v1 += bias[col + 1];
                    if (EPI == 3) { v0 = gelu_f(v0); v1 = gelu_f(v1); }
                    *(__half2*)&Ch[(size_t)rowg * N + col] = __floats2half2_rn(v0, v1);
                } else {
                    if (EPI >= 1) { v0 += bias[col]; v1 += bias[col + 1]; }
                    if (EPI == 2) {
                        v0 += R[(size_t)rowg * N + col];
                        v1 += R[(size_t)rowg * N + col + 1];
                    }
                    float2 o = make_float2(v0, v1);
                    *(float2*)&C[(size_t)rowg * N + col] = o;
                }
            }
        }
    }
}

// ---------------- embedding: x = wte[idx] + wpe[t] ----------------
__global__ void embed_kernel(const int* __restrict__ idx,
                             const float* __restrict__ wte,
                             const float* __restrict__ wpe,
                             float* __restrict__ x) {
    int i = blockIdx.x * blockDim.x + threadIdx.x;
    if (i >= MROW * EMB) return;
    int row = i / EMB;
    int e = i - row * EMB;
    int t = row % TLEN;
    x[i] = wte[(size_t)idx[row] * EMB + e] + wpe[(size_t)t * EMB + e];
}

// ---------------- layernorm: fp32 in, fp16 out ----------------
__global__ void __launch_bounds__(256) ln_kernel(const float* __restrict__ x,
                                                 const float* __restrict__ w,
                                                 const float* __restrict__ b,
                                                 __half* __restrict__ o16) {
    __shared__ float red[8];
    __shared__ float s_mean, s_var;
    int row = blockIdx.x;
    int tid = threadIdx.x;
    int warp = tid >> 5, lane = tid & 31;
    const float* xr = x + (size_t)row * EMB;

    float v0 = xr[tid], v1 = xr[tid + 256], v2 = xr[tid + 512];
    float s = v0 + v1 + v2;
#pragma unroll
    for (int o = 16; o; o >>= 1) s += __shfl_xor_sync(0xffffffffu, s, o);
    if (lane == 0) red[warp] = s;
    __syncthreads();
    if (tid == 0) {
        float t = 0.f;
#pragma unroll
        for (int i = 0; i < 8; i++) t += red[i];
        s_mean = t * (1.0f / EMB);
    }
    __syncthreads();
    float m = s_mean;
    float d0 = v0 - m, d1 = v1 - m, d2 = v2 - m;
    float q = d0 * d0 + d1 * d1 + d2 * d2;
#pragma unroll
    for (int o = 16; o; o >>= 1) q += __shfl_xor_sync(0xffffffffu, q, o);
    if (lane == 0) red[warp] = q;
    __syncthreads();
    if (tid == 0) {
        float t = 0.f;
#pragma unroll
        for (int i = 0; i < 8; i++) t += red[i];
        s_var = t * (1.0f / EMB);
    }
    __syncthreads();
    float r = rsqrtf(s_var + 1e-5f);
    size_t base = (size_t)row * EMB;
#pragma unroll
    for (int u = 0; u < 3; u++) {
        int e = tid + u * 256;
        float d = (u == 0 ? d0 : (u == 1 ? d1 : d2));
        o16[base + e] = __float2half_rn(d * r * w[e] + b[e]);
    }
}

// ---------------- flash attention: tensor cores, 64q x 64k tiles ----------------
// grid (48, 16): blockIdx.x = b*12+h, blockIdx.y = query block. 4 warps, 16 q-rows each.
#define ASTR 144   // smem row stride: 16-aligned; 144*i mod 128 covers 8 distinct banks

__global__ void __launch_bounds__(128) fattn_kernel(const __half* __restrict__ qkv,
                                                    __half* __restrict__ y) {
    __shared__ __align__(16) char smem[3 * 64 * ASTR];
    const uint32_t sQ = smem_u32(smem);
    const uint32_t sK = sQ + 64 * ASTR;
    const uint32_t sV = sK + 64 * ASTR;
    const int tid = threadIdx.x, warp = tid >> 5, lane = tid & 31;
    const int g = lane >> 2, t4 = lane & 3;
    const int bh = blockIdx.x;
    const int b = bh / NHEAD, h = bh % NHEAD;
    const int qb = blockIdx.y;
    const size_t row0g = (size_t)(b * TLEN);

    // ---- load Q tile (64 q-rows x 64 d) ----
#pragma unroll
    for (int u = 0; u < 4; u++) {
        int id = tid + u * 128;           // 512 16B chunks
        int row = id >> 3, c = id & 7;
        const uint4* src = (const uint4*)(qkv + (row0g + qb * 64 + row) * (3 * EMB) + h * HEADD + c * 8);
        *(uint4*)(smem + row * ASTR + c * 16) = *src;
    }
    __syncthreads();

    // preload Q fragments (reused across all key chunks)
    uint32_t qf[4][4];
    {
        uint32_t aoffQ = sQ + (warp * 16 + (lane & 15)) * ASTR + ((lane >> 4) * 16);
#pragma unroll
        for (int ks = 0; ks < 4; ks++) ldsm_x4(aoffQ + ks * 32, qf[ks]);
    }

    float m0 = -1e30f, m1 = -1e30f, l0 = 0.f, l1 = 0.f;
    float O[8][4];
#pragma unroll
    for (int j = 0; j < 8; j++)
#pragma unroll
        for (int e = 0; e < 4; e++) O[j][e] = 0.f;

    const uint32_t boffK = sK + (lane & 7) * ASTR + ((lane >> 3) & 1) * 16;
    const uint32_t boffV = sV + ((lane & 7) + ((lane >> 3) & 1) * 8) * ASTR;

    for (int c = 0; c <= qb; c++) {
        __syncthreads();
        // ---- load K and V chunks (64 keys x 64 d each) ----
#pragma unroll
        for (int u = 0; u < 4; u++) {
            int id = tid + u * 128;
            int row = id >> 3, cc = id & 7;
            const __half* src = qkv + (row0g + c * 64 + row) * (3 * EMB) + EMB + h * HEADD + cc * 8;
            *(uint4*)(smem + 64 * ASTR + row * ASTR + cc * 16) = *(const uint4*)src;
            *(uint4*)(smem + 128 * ASTR + row * ASTR + cc * 16) = *(const uint4*)(src + EMB);
        }
        __syncthreads();

        // ---- S = Q @ K^T (fp32 acc) ----
        float S[8][4];
#pragma unroll
        for (int j = 0; j < 8; j++)
#pragma unroll
            for (int e = 0; e < 4; e++) S[j][e] = 0.f;
#pragma unroll
        for (int ks = 0; ks < 4; ks++) {
#pragma unroll
            for (int j = 0; j < 8; j++) {
                uint32_t bf[2];
                ldsm_x2(boffK + j * (8 * ASTR) + ks * 32, bf);
                mma_fp16(S[j], qf[ks], bf);
            }
        }
        // scale
#pragma unroll
        for (int j = 0; j < 8; j++)
#pragma unroll
            for (int e = 0; e < 4; e++) S[j][e] *= 0.125f;
        // causal mask on diagonal chunk
        if (c == qb) {
            int q0l = warp * 16 + g, q1l = q0l + 8;
#pragma unroll
            for (int j = 0; j < 8; j++) {
                int k0 = j * 8 + 2 * t4;
                if (k0 > q0l)     S[j][0] = -1e30f;
                if (k0 + 1 > q0l) S[j][1] = -1e30f;
                if (k0 > q1l)     S[j][2] = -1e30f;
                if (k0 + 1 > q1l) S[j][3] = -1e30f;
            }
        }
        // row max (quad reduce: fragment row lives in 4 lanes)
        float rm0 = -1e30f, rm1 = -1e30f;
#pragma unroll
        for (int j = 0; j < 8; j++) {
            rm0 = fmaxf(rm0, fmaxf(S[j][0], S[j][1]));
            rm1 = fmaxf(rm1, fmaxf(S[j][2], S[j][3]));
        }
        rm0 = fmaxf(rm0, __shfl_xor_sync(0xffffffffu, rm0, 1));
        rm0 = fmaxf(rm0, __shfl_xor_sync(0xffffffffu, rm0, 2));
        rm1 = fmaxf(rm1, __shfl_xor_sync(0xffffffffu, rm1, 1));
        rm1 = fmaxf(rm1, __shfl_xor_sync(0xffffffffu, rm1, 2));
        float mn0 = fmaxf(m0, rm0), mn1 = fmaxf(m1, rm1);
        float corr0 = __expf(m0 - mn0), corr1 = __expf(m1 - mn1);
        m0 = mn0; m1 = mn1;
        // P = exp(S - m), row sums
        float rs0 = 0.f, rs1 = 0.f;
#pragma unroll
        for (int j = 0; j < 8; j++) {
            S[j][0] = __expf(S[j][0] - mn0);
            S[j][1] = __expf(S[j][1] - mn0);
            S[j][2] = __expf(S[j][2] - mn1);
            S[j][3] = __expf(S[j][3] - mn1);
            rs0 += S[j][0] + S[j][1];
            rs1 += S[j][2] + S[j][3];
        }
        rs0 += __shfl_xor_sync(0xffffffffu, rs0, 1);
        rs0 += __shfl_xor_sync(0xffffffffu, rs0, 2);
        rs1 += __shfl_xor_sync(0xffffffffu, rs1, 1);
        rs1 += __shfl_xor_sync(0xffffffffu, rs1, 2);
        l0 = l0 * corr0 + rs0;
        l1 = l1 * corr1 + rs1;
        // rescale O
#pragma unroll
        for (int j = 0; j < 8; j++) {
            O[j][0] *= corr0; O[j][1] *= corr0;
            O[j][2] *= corr1; O[j][3] *= corr1;
        }
        // ---- O += P @ V ----
#pragma unroll
        for (int kc = 0; kc < 4; kc++) {
            uint32_t pa[4];
            pa[0] = packh2(S[2 * kc][0],     S[2 * kc][1]);
            pa[1] = packh2(S[2 * kc][2],     S[2 * kc][3]);
            pa[2] = packh2(S[2 * kc + 1][0], S[2 * kc + 1][1]);
            pa[3] = packh2(S[2 * kc + 1][2], S[2 * kc + 1][3]);
#pragma unroll
            for (int jd = 0; jd < 8; jd++) {
                uint32_t bv[2];
                ldsm_x2t(boffV + kc * (16 * ASTR) + jd * 16, bv);
                mma_fp16(O[jd], pa, bv);
            }
        }
    }

    // ---- write O / l ----
    float i0 = 1.0f / l0, i1 = 1.0f / l1;
    int qrow = qb * 64 + warp * 16 + g;
    size_t ybase = (row0g + qrow) * EMB + h * HEADD;
#pragma unroll
    for (int jd = 0; jd < 8; jd++) {
        int col = jd * 8 + 2 * t4;
        *(__half2*)&y[ybase + col] = __floats2half2_rn(O[jd][0] * i0, O[jd][1] * i0);
        *(__half2*)&y[ybase + 8 * EMB + col] = __floats2half2_rn(O[jd][2] * i1, O[jd][3] * i1);
    }
}

// ---------------- host launch ----------------
extern "C" void kernel_launch(void* const* d_in, const int* in_sizes, int n_in,
                              void* d_out, int out_size) {
    (void)in_sizes; (void)n_in; (void)out_size;
    const int*   x_idx  = (const int*)d_in[0];
    const float* wte    = (const float*)d_in[1];
    const float* wpe    = (const float*)d_in[2];
    const float* ln1_w  = (const float*)d_in[3];
    const float* ln1_b  = (const float*)d_in[4];
    const float* attn_w = (const float*)d_in[5];
    const float* attn_b = (const float*)d_in[6];
    const float* proj_w = (const float*)d_in[7];
    const float* proj_b = (const float*)d_in[8];
    const float* ln2_w  = (const float*)d_in[9];
    const float* ln2_b  = (const float*)d_in[10];
    const float* fc1_w  = (const float*)d_in[11];
    const float* fc1_b  = (const float*)d_in[12];
    const float* fc2_w  = (const float*)d_in[13];
    const float* fc2_b  = (const float*)d_in[14];
    const float* lnf_w  = (const float*)d_in[15];
    const float* lnf_b  = (const float*)d_in[16];
    float* out = (float*)d_out;

    float *gx;
    __half *gh, *gqkv, *gy, *gf1;
    __half *wq, *wp, *w1, *w2, *wt;
    cudaGetSymbolAddress((void**)&gx,   g_x);
    cudaGetSymbolAddress((void**)&gh,   g_h);
    cudaGetSymbolAddress((void**)&gqkv, g_qkv16);
    cudaGetSymbolAddress((void**)&gy,   g_y);
    cudaGetSymbolAddress((void**)&gf1,  g_f1);
    cudaGetSymbolAddress((void**)&wq,   g_wqkv);
    cudaGetSymbolAddress((void**)&wp,   g_wproj);
    cudaGetSymbolAddress((void**)&w1,   g_wf1);
    cudaGetSymbolAddress((void**)&w2,   g_wf2);
    cudaGetSymbolAddress((void**)&wt,   g_wte16);

    cudaFuncSetAttribute(tc_gemm<5, 0>, cudaFuncAttributeMaxDynamicSharedMemorySize, GEMM_SMEM);
    cudaFuncSetAttribute(tc_gemm<2, 0>, cudaFuncAttributeMaxDynamicSharedMemorySize, GEMM_SMEM);
    cudaFuncSetAttribute(tc_gemm<3, 0>, cudaFuncAttributeMaxDynamicSharedMemorySize, GEMM_SMEM);
    cudaFuncSetAttribute(tc_gemm<0, 1>, cudaFuncAttributeMaxDynamicSharedMemorySize, GEMM_SMEM);

    // launch order keeps the first qkv GEMM at launch #6 for ncu (-s 5 -c 1)
    embed_kernel<<<(MROW * EMB + 255) / 256, 256>>>(x_idx, wte, wpe, gx);          // 1
    cvtT2_kernel<<<dim3(96, 24, 2 * NLAYER), 256>>>(                               // 2
        attn_w, wq, EMB, 3 * EMB, fc1_w, w1, EMB, 4 * EMB);
    cvtT2_kernel<<<dim3(24, 96, 2 * NLAYER), 256>>>(                               // 3
        proj_w, wp, EMB, EMB, fc2_w, w2, 4 * EMB, EMB);
    cvt_kernel<<<(VOCAB * EMB + 255) / 256, 256>>>(wte, wt, VOCAB * EMB);          // 4

    for (int l = 0; l < NLAYER; l++) {
        ln_kernel<<<MROW, 256>>>(gx, ln1_w + (size_t)l * EMB, ln1_b + (size_t)l * EMB, gh);  // 5

        // qkv = h @ attn_w + attn_b -> fp16  (N=2304 -> 18 n-tiles)               // 6 <- ncu
        tc_gemm<5, 0><<<32 * 18, 128, GEMM_SMEM>>>(
            gh, wq + (size_t)l * 3 * EMB * EMB,
            attn_b + (size_t)l * 3 * EMB, nullptr, nullptr, gqkv, 3 * EMB, EMB);

        fattn_kernel<<<dim3(BATCH * NHEAD, TLEN / 64), 128>>>(gqkv, gy);

        // x = x + y @ proj_w + proj_b  (N=768 -> 6 n-tiles)
        tc_gemm<2, 0><<<32 * 6, 128, GEMM_SMEM>>>(
            gy, wp + (size_t)l * EMB * EMB,
            proj_b + (size_t)l * EMB, gx, gx, nullptr, EMB, EMB);

        ln_kernel<<<MROW, 256>>>(gx, ln2_w + (size_t)l * EMB, ln2_b + (size_t)l * EMB, gh);

        // f1 = gelu(h @ fc1_w + fc1_b) -> fp16  (N=3072 -> 24 n-tiles)
        tc_gemm<3, 0><<<32 * 24, 128, GEMM_SMEM>>>(
            gh, w1 + (size_t)l * 4 * EMB * EMB,
            fc1_b + (size_t)l * 4 * EMB, nullptr, nullptr, gf1, 4 * EMB, EMB);

        // x = x + f1 @ fc2_w + fc2_b   (N=768, K=3072 -> 6 n-tiles)
        tc_gemm<2, 0><<<32 * 6, 128, GEMM_SMEM>>>(
            gf1, w2 + (size_t)l * 4 * EMB * EMB,
            fc2_b + (size_t)l * EMB, gx, gx, nullptr, EMB, 4 * EMB);
    }

    ln_kernel<<<MROW, 256>>>(gx, lnf_w, lnf_b, gh);

    // logits = h @ wte^T  (N=50257 -> 393 n-tiles, ragged)
    tc_gemm<0, 1><<<32 * 393, 128, GEMM_SMEM>>>(
        gh, wt, nullptr, nullptr, out, nullptr, VOCAB, EMB);
}

// round 13
// speedup vs baseline: 8.7476x; 1.0255x over previous
#include <cuda_runtime.h>
#include <cuda_fp16.h>
#include <math.h>
#include <stdint.h>

// GPT-2 small config
#define BATCH 4
#define TLEN  1024
#define EMB   768
#define NLAYER 12
#define VOCAB 50257
#define NHEAD 12
#define HEADD 64
#define MROW  (BATCH * TLEN)   // 4096

// ---------------- scratch (device globals; no allocation allowed) ----------------
__device__ float g_x[MROW * EMB];        // residual stream (fp32)

// fp16 activations
__device__ __half g_h[MROW * EMB];
__device__ __half g_qkv16[MROW * 3 * EMB];
__device__ __half g_y[MROW * EMB];
__device__ __half g_f1[MROW * 4 * EMB];

// fp16 weights, stored [N][K] (K-major rows) for ldmatrix col access
__device__ __half g_wqkv[NLAYER * 3 * EMB * EMB];
__device__ __half g_wproj[NLAYER * EMB * EMB];
__device__ __half g_wf1[NLAYER * 4 * EMB * EMB];
__device__ __half g_wf2[NLAYER * 4 * EMB * EMB];
__device__ __half g_wte16[VOCAB * EMB];

// ======================= helpers =======================
__device__ __forceinline__ uint32_t smem_u32(const void* p) {
    uint32_t a;
    asm("{ .reg .u64 t; cvta.to.shared.u64 t, %1; cvt.u32.u64 %0, t; }"
        : "=r"(a) : "l"(p));
    return a;
}
__device__ __forceinline__ void ldsm_x4(uint32_t addr, uint32_t* r) {
    asm volatile("ldmatrix.sync.aligned.m8n8.x4.shared.b16 {%0,%1,%2,%3}, [%4];"
                 : "=r"(r[0]), "=r"(r[1]), "=r"(r[2]), "=r"(r[3]) : "r"(addr));
}
__device__ __forceinline__ void ldsm_x2(uint32_t addr, uint32_t* r) {
    asm volatile("ldmatrix.sync.aligned.m8n8.x2.shared.b16 {%0,%1}, [%2];"
                 : "=r"(r[0]), "=r"(r[1]) : "r"(addr));
}
__device__ __forceinline__ void ldsm_x2t(uint32_t addr, uint32_t* r) {
    asm volatile("ldmatrix.sync.aligned.m8n8.x2.trans.shared.b16 {%0,%1}, [%2];"
                 : "=r"(r[0]), "=r"(r[1]) : "r"(addr));
}
__device__ __forceinline__ void mma_fp16(float* d, const uint32_t* a, const uint32_t* b) {
    asm volatile(
        "mma.sync.aligned.m16n8k16.row.col.f32.f16.f16.f32 "
        "{%0,%1,%2,%3}, {%4,%5,%6,%7}, {%8,%9}, {%0,%1,%2,%3};"
        : "+f"(d[0]), "+f"(d[1]), "+f"(d[2]), "+f"(d[3])
        : "r"(a[0]), "r"(a[1]), "r"(a[2]), "r"(a[3]), "r"(b[0]), "r"(b[1]));
}
__device__ __forceinline__ void cp16(uint32_t saddr, const void* g) {
    asm volatile("cp.async.cg.shared.global [%0], [%1], 16;" :: "r"(saddr), "l"(g));
}
__device__ __forceinline__ void cp16z(uint32_t saddr, const void* g, int ok) {
    int sz = ok ? 16 : 0;
    asm volatile("cp.async.cg.shared.global [%0], [%1], 16, %2;" :: "r"(saddr), "l"(g), "r"(sz));
}
#define CP_COMMIT() asm volatile("cp.async.commit_group;" ::: "memory")
#define CP_WAIT1()  asm volatile("cp.async.wait_group 1;" ::: "memory")

__device__ __forceinline__ uint32_t packh2(float a, float b) {
    __half2 t = __floats2half2_rn(a, b);
    return reinterpret_cast<uint32_t&>(t);
}
__device__ __forceinline__ float gelu_f(float x) {
    return 0.5f * x * (1.0f + erff(x * 0.7071067811865476f));
}

// ======================= weight convert kernels =======================
// vectorized elementwise convert: 4 floats -> 4 halves per thread
__global__ void cvt_kernel(const float* __restrict__ src,
                           __half* __restrict__ dst, int n4) {
    int i = blockIdx.x * blockDim.x + threadIdx.x;
    if (i >= n4) return;
    float4 v = ((const float4*)src)[i];
    uint2 o;
    o.x = packh2(v.x, v.y);
    o.y = packh2(v.z, v.w);
    ((uint2*)dst)[i] = o;
}

// transpose+convert for TWO weight families in one launch.
__global__ void __launch_bounds__(256) cvtT2_kernel(
    const float* __restrict__ srcA, __half* __restrict__ dstA, int KA, int NA,
    const float* __restrict__ srcB, __half* __restrict__ dstB, int KB, int NB) {
    __shared__ float t[32][33];
    int z = blockIdx.z;
    const float* src;  __half* dst;  int K, N;
    if (z < NLAYER) {
        src = srcA + (size_t)z * KA * NA;  dst = dstA + (size_t)z * KA * NA;
        K = KA;  N = NA;
    } else {
        src = srcB + (size_t)(z - NLAYER) * KB * NB;  dst = dstB + (size_t)(z - NLAYER) * KB * NB;
        K = KB;  N = NB;
    }
    int bn = blockIdx.x * 32, bk = blockIdx.y * 32;
    if (bn >= N || bk >= K) return;
    int tx = threadIdx.x & 31, ty = threadIdx.x >> 5;
#pragma unroll
    for (int i = 0; i < 4; i++)
        t[ty + i * 8][tx] = src[(size_t)(bk + ty + i * 8) * N + bn + tx];
    __syncthreads();
#pragma unroll
    for (int i = 0; i < 4; i++) {
        int n = bn + ty + i * 8;
        int k = bk + tx;
        dst[(size_t)n * K + k] = __float2half_rn(t[tx][ty + i * 8]);
    }
}

// ======================= mma.sync fp16 GEMM =======================
// EPI: 0=none(fp32 C), 1=+bias(fp32), 2=+bias+residual(fp32),
//      3=+bias,GELU->fp16, 5=+bias->fp16
// RAGGED: guard B rows / C cols against N (lm_head)
// MT: m-tile height in 32-row units (4 -> 128-row tile, 2 -> 64-row tile)
#define TCSTRIDE 80

template <int EPI, int RAGGED, int MT>
__global__ void __launch_bounds__(128) tc_gemm(const __half* __restrict__ A,
                                               const __half* __restrict__ B,
                                               const float* __restrict__ bias,
                                               const float* __restrict__ R,
                                               float* __restrict__ C,
                                               __half* __restrict__ Ch,
                                               int N, int K) {
    constexpr int TILE_M = MT * 32;
    constexpr int REG_B = TILE_M * TCSTRIDE;           // A region bytes
    constexpr int STAGE = REG_B + 128 * TCSTRIDE;      // + B region
    constexpr int MTILES = MROW / TILE_M;

    extern __shared__ char sm[];
    const uint32_t sbase = smem_u32(sm);
    const int tid = threadIdx.x;
    const int warp = tid >> 5, lane = tid & 31;

    // m-inner ordering: consecutive CTAs share the same B tile (L2 reuse)
    const int m0 = (blockIdx.x % MTILES) * TILE_M;
    const int n0 = (blockIdx.x / MTILES) * 128;

    const int warpM = (warp >> 1) * (TILE_M / 2);
    const int warpN = (warp & 1) * 64;

    float acc[MT][8][4];
#pragma unroll
    for (int i = 0; i < MT; i++)
#pragma unroll
        for (int j = 0; j < 8; j++)
#pragma unroll
            for (int c = 0; c < 4; c++) acc[i][j][c] = 0.f;

    const int NK = K >> 5;

    auto fill = [&](int s) {
        const uint32_t st = sbase + (s & 1) * STAGE;
        const int k0 = s << 5;
        // A: TILE_M rows x 4 chunks
#pragma unroll
        for (int u = 0; u < MT; u++) {
            int id = tid + (u << 7);
            int row = id >> 2, c = id & 3;
            cp16(st + row * TCSTRIDE + c * 16,
                 A + (size_t)(m0 + row) * K + k0 + c * 8);
        }
        // B: 128 rows x 4 chunks
#pragma unroll
        for (int u = 0; u < 4; u++) {
            int id = tid + (u << 7);
            int row = id >> 2, c = id & 3;
            uint32_t so = st + REG_B + row * TCSTRIDE + c * 16;
            int gn = n0 + row;
            if (RAGGED) {
                int ok = gn < N;
                int gnc = ok ? gn : 0;
                cp16z(so, B + (size_t)gnc * K + k0 + c * 8, ok);
            } else {
                cp16(so, B + (size_t)gn * K + k0 + c * 8);
            }
        }
    };

    fill(0); CP_COMMIT();
    fill(1); CP_COMMIT();

    const uint32_t aoff = (uint32_t)((warpM + (lane & 15)) * TCSTRIDE + ((lane >> 4) * 8) * 2);
    const uint32_t boff = (uint32_t)((warpN + (lane & 7)) * TCSTRIDE + (((lane >> 3) & 1) * 8) * 2);

    for (int kt = 0; kt < NK; kt++) {
        CP_WAIT1();
        __syncthreads();
        const uint32_t st = sbase + (kt & 1) * STAGE;

#pragma unroll
        for (int ks = 0; ks < 2; ks++) {
            uint32_t af[MT][4];
#pragma unroll
            for (int mt = 0; mt < MT; mt++)
                ldsm_x4(st + aoff + mt * (16 * TCSTRIDE) + (ks * 32), af[mt]);
#pragma unroll
            for (int nh = 0; nh < 2; nh++) {
                uint32_t bf[4][2];
#pragma unroll
                for (int j = 0; j < 4; j++)
                    ldsm_x2(st + REG_B + boff + (nh * 4 + j) * (8 * TCSTRIDE) + (ks * 32), bf[j]);
#pragma unroll
                for (int mt = 0; mt < MT; mt++)
#pragma unroll
                    for (int j = 0; j < 4; j++)
                        mma_fp16(acc[mt][nh * 4 + j], af[mt], bf[j]);
            }
        }
        __syncthreads();
        if (kt + 2 < NK) fill(kt + 2);
        CP_COMMIT();
    }

    // ---- epilogue ----
    const int g = lane >> 2, t4 = lane & 3;
#pragma unroll
    for (int mt = 0; mt < MT; mt++) {
#pragma unroll
        for (int nt = 0; nt < 8; nt++) {
            int col = n0 + warpN + nt * 8 + 2 * t4;
            int row0 = m0 + warpM + mt * 16 + g;
#pragma unroll
            for (int h = 0; h < 2; h++) {
                int rowg = row0 + h * 8;
                float v0 = acc[mt][nt][2 * h];
                float v1 = acc[mt][nt][2 * h + 1];
                if (RAGGED) {
                    if (col < N) {
                        if (EPI >= 1) v0 += bias[col];
                        C[(size_t)rowg * N + col] = v0;
                    }
                    if (col + 1 < N) {
                        if (EPI >= 1) v1 += bias[col + 1];
                        C[(size_t)rowg * N + col + 1] = v1;
                    }
                } else if (EPI == 3 || EPI == 5) {
                    v0 += bias[col]; v1 += bias[col + 1];
                    if (EPI == 3) { v0 = gelu_f(v0); v1 = gelu_f(v1); }
                    *(__half2*)&Ch[(size_t)rowg * N + col] = __floats2half2_rn(v0, v1);
                } else {
                    if (EPI >= 1) { v0 += bias[col]; v1 += bias[col + 1]; }
                    if (EPI == 2) {
                        v0 += R[(size_t)rowg * N + col];
                        v1 += R[(size_t)rowg * N + col + 1];
                    }
                    float2 o = make_float2(v0, v1);
                    *(float2*)&C[(size_t)rowg * N + col] = o;
                }
            }
        }
    }
}

#define SMEM_MT4 (2 * (128 * TCSTRIDE + 128 * TCSTRIDE))   // 40960
#define SMEM_MT2 (2 * (64 * TCSTRIDE + 128 * TCSTRIDE))    // 30720

// ---------------- embedding: x = wte[idx] + wpe[t] ----------------
__global__ void embed_kernel(const int* __restrict__ idx,
                             const float* __restrict__ wte,
                             const float* __restrict__ wpe,
                             float* __restrict__ x) {
    int i = blockIdx.x * blockDim.x + threadIdx.x;
    if (i >= MROW * EMB) return;
    int row = i / EMB;
    int e = i - row * EMB;
    int t = row % TLEN;
    x[i] = wte[(size_t)idx[row] * EMB + e] + wpe[(size_t)t * EMB + e];
}

// ---------------- layernorm: fp32 in, fp16 out ----------------
__global__ void __launch_bounds__(256) ln_kernel(const float* __restrict__ x,
                                                 const float* __restrict__ w,
                                                 const float* __restrict__ b,
                                                 __half* __restrict__ o16) {
    __shared__ float red[8];
    __shared__ float s_mean, s_var;
    int row = blockIdx.x;
    int tid = threadIdx.x;
    int warp = tid >> 5, lane = tid & 31;
    const float* xr = x + (size_t)row * EMB;

    float v0 = xr[tid], v1 = xr[tid + 256], v2 = xr[tid + 512];
    float s = v0 + v1 + v2;
#pragma unroll
    for (int o = 16; o; o >>= 1) s += __shfl_xor_sync(0xffffffffu, s, o);
    if (lane == 0) red[warp] = s;
    __syncthreads();
    if (tid == 0) {
        float t = 0.f;
#pragma unroll
        for (int i = 0; i < 8; i++) t += red[i];
        s_mean = t * (1.0f / EMB);
    }
    __syncthreads();
    float m = s_mean;
    float d0 = v0 - m, d1 = v1 - m, d2 = v2 - m;
    float q = d0 * d0 + d1 * d1 + d2 * d2;
#pragma unroll
    for (int o = 16; o; o >>= 1) q += __shfl_xor_sync(0xffffffffu, q, o);
    if (lane == 0) red[warp] = q;
    __syncthreads();
    if (tid == 0) {
        float t = 0.f;
#pragma unroll
        for (int i = 0; i < 8; i++) t += red[i];
        s_var = t * (1.0f / EMB);
    }
    __syncthreads();
    float r = rsqrtf(s_var + 1e-5f);
    size_t base = (size_t)row * EMB;
#pragma unroll
    for (int u = 0; u < 3; u++) {
        int e = tid + u * 256;
        float d = (u == 0 ? d0 : (u == 1 ? d1 : d2));
        o16[base + e] = __float2half_rn(d * r * w[e] + b[e]);
    }
}

// ---------------- flash attention: tensor cores, 64q x 64k tiles ----------------
#define ASTR 144

__global__ void __launch_bounds__(128) fattn_kernel(const __half* __restrict__ qkv,
                                                    __half* __restrict__ y) {
    __shared__ __align__(16) char smem[3 * 64 * ASTR];
    const uint32_t sQ = smem_u32(smem);
    const uint32_t sK = sQ + 64 * ASTR;
    const uint32_t sV = sK + 64 * ASTR;
    const int tid = threadIdx.x, warp = tid >> 5, lane = tid & 31;
    const int g = lane >> 2, t4 = lane & 3;
    const int bh = blockIdx.x;
    const int b = bh / NHEAD, h = bh % NHEAD;
    const int qb = blockIdx.y;
    const size_t row0g = (size_t)(b * TLEN);

#pragma unroll
    for (int u = 0; u < 4; u++) {
        int id = tid + u * 128;
        int row = id >> 3, c = id & 7;
        const uint4* src = (const uint4*)(qkv + (row0g + qb * 64 + row) * (3 * EMB) + h * HEADD + c * 8);
        *(uint4*)(smem + row * ASTR + c * 16) = *src;
    }
    __syncthreads();

    uint32_t qf[4][4];
    {
        uint32_t aoffQ = sQ + (warp * 16 + (lane & 15)) * ASTR + ((lane >> 4) * 16);
#pragma unroll
        for (int ks = 0; ks < 4; ks++) ldsm_x4(aoffQ + ks * 32, qf[ks]);
    }

    float m0 = -1e30f, m1 = -1e30f, l0 = 0.f, l1 = 0.f;
    float O[8][4];
#pragma unroll
    for (int j = 0; j < 8; j++)
#pragma unroll
        for (int e = 0; e < 4; e++) O[j][e] = 0.f;

    const uint32_t boffK = sK + (lane & 7) * ASTR + ((lane >> 3) & 1) * 16;
    const uint32_t boffV = sV + ((lane & 7) + ((lane >> 3) & 1) * 8) * ASTR;

    for (int c = 0; c <= qb; c++) {
        __syncthreads();
#pragma unroll
        for (int u = 0; u < 4; u++) {
            int id = tid + u * 128;
            int row = id >> 3, cc = id & 7;
            const __half* src = qkv + (row0g + c * 64 + row) * (3 * EMB) + EMB + h * HEADD + cc * 8;
            *(uint4*)(smem + 64 * ASTR + row * ASTR + cc * 16) = *(const uint4*)src;
            *(uint4*)(smem + 128 * ASTR + row * ASTR + cc * 16) = *(const uint4*)(src + EMB);
        }
        __syncthreads();

        float S[8][4];
#pragma unroll
        for (int j = 0; j < 8; j++)
#pragma unroll
            for (int e = 0; e < 4; e++) S[j][e] = 0.f;
#pragma unroll
        for (int ks = 0; ks < 4; ks++) {
#pragma unroll
            for (int j = 0; j < 8; j++) {
                uint32_t bf[2];
                ldsm_x2(boffK + j * (8 * ASTR) + ks * 32, bf);
                mma_fp16(S[j], qf[ks], bf);
            }
        }
#pragma unroll
        for (int j = 0; j < 8; j++)
#pragma unroll
            for (int e = 0; e < 4; e++) S[j][e] *= 0.125f;
        if (c == qb) {
            int q0l = warp * 16 + g, q1l = q0l + 8;
#pragma unroll
            for (int j = 0; j < 8; j++) {
                int k0 = j * 8 + 2 * t4;
                if (k0 > q0l)     S[j][0] = -1e30f;
                if (k0 + 1 > q0l) S[j][1] = -1e30f;
                if (k0 > q1l)     S[j][2] = -1e30f;
                if (k0 + 1 > q1l) S[j][3] = -1e30f;
            }
        }
        float rm0 = -1e30f, rm1 = -1e30f;
#pragma unroll
        for (int j = 0; j < 8; j++) {
            rm0 = fmaxf(rm0, fmaxf(S[j][0], S[j][1]));
            rm1 = fmaxf(rm1, fmaxf(S[j][2], S[j][3]));
        }
        rm0 = fmaxf(rm0, __shfl_xor_sync(0xffffffffu, rm0, 1));
        rm0 = fmaxf(rm0, __shfl_xor_sync(0xffffffffu, rm0, 2));
        rm1 = fmaxf(rm1, __shfl_xor_sync(0xffffffffu, rm1, 1));
        rm1 = fmaxf(rm1, __shfl_xor_sync(0xffffffffu, rm1, 2));
        float mn0 = fmaxf(m0, rm0), mn1 = fmaxf(m1, rm1);
        float corr0 = __expf(m0 - mn0), corr1 = __expf(m1 - mn1);
        m0 = mn0; m1 = mn1;
        float rs0 = 0.f, rs1 = 0.f;
#pragma unroll
        for (int j = 0; j < 8; j++) {
            S[j][0] = __expf(S[j][0] - mn0);
            S[j][1] = __expf(S[j][1] - mn0);
            S[j][2] = __expf(S[j][2] - mn1);
            S[j][3] = __expf(S[j][3] - mn1);
            rs0 += S[j][0] + S[j][1];
            rs1 += S[j][2] + S[j][3];
        }
        rs0 += __shfl_xor_sync(0xffffffffu, rs0, 1);
        rs0 += __shfl_xor_sync(0xffffffffu, rs0, 2);
        rs1 += __shfl_xor_sync(0xffffffffu, rs1, 1);
        rs1 += __shfl_xor_sync(0xffffffffu, rs1, 2);
        l0 = l0 * corr0 + rs0;
        l1 = l1 * corr1 + rs1;
#pragma unroll
        for (int j = 0; j < 8; j++) {
            O[j][0] *= corr0; O[j][1] *= corr0;
            O[j][2] *= corr1; O[j][3] *= corr1;
        }
#pragma unroll
        for (int kc = 0; kc < 4; kc++) {
            uint32_t pa[4];
            pa[0] = packh2(S[2 * kc][0],     S[2 * kc][1]);
            pa[1] = packh2(S[2 * kc][2],     S[2 * kc][3]);
            pa[2] = packh2(S[2 * kc + 1][0], S[2 * kc + 1][1]);
            pa[3] = packh2(S[2 * kc + 1][2], S[2 * kc + 1][3]);
#pragma unroll
            for (int jd = 0; jd < 8; jd++) {
                uint32_t bv[2];
                ldsm_x2t(boffV + kc * (16 * ASTR) + jd * 16, bv);
                mma_fp16(O[jd], pa, bv);
            }
        }
    }

    float i0 = 1.0f / l0, i1 = 1.0f / l1;
    int qrow = qb * 64 + warp * 16 + g;
    size_t ybase = (row0g + qrow) * EMB + h * HEADD;
#pragma unroll
    for (int jd = 0; jd < 8; jd++) {
        int col = jd * 8 + 2 * t4;
        *(__half2*)&y[ybase + col] = __floats2half2_rn(O[jd][0] * i0, O[jd][1] * i0);
        *(__half2*)&y[ybase + 8 * EMB + col] = __floats2half2_rn(O[jd][2] * i1, O[jd][3] * i1);
    }
}

// ---------------- host launch ----------------
extern "C" void kernel_launch(void* const* d_in, const int* in_sizes, int n_in,
                              void* d_out, int out_size) {
    (void)in_sizes; (void)n_in; (void)out_size;
    const int*   x_idx  = (const int*)d_in[0];
    const float* wte    = (const float*)d_in[1];
    const float* wpe    = (const float*)d_in[2];
    const float* ln1_w  = (const float*)d_in[3];
    const float* ln1_b  = (const float*)d_in[4];
    const float* attn_w = (const float*)d_in[5];
    const float* attn_b = (const float*)d_in[6];
    const float* proj_w = (const float*)d_in[7];
    const float* proj_b = (const float*)d_in[8];
    const float* ln2_w  = (const float*)d_in[9];
    const float* ln2_b  = (const float*)d_in[10];
    const float* fc1_w  = (const float*)d_in[11];
    const float* fc1_b  = (const float*)d_in[12];
    const float* fc2_w  = (const float*)d_in[13];
    const float* fc2_b  = (const float*)d_in[14];
    const float* lnf_w  = (const float*)d_in[15];
    const float* lnf_b  = (const float*)d_in[16];
    float* out = (float*)d_out;

    float *gx;
    __half *gh, *gqkv, *gy, *gf1;
    __half *wq, *wp, *w1, *w2, *wt;
    cudaGetSymbolAddress((void**)&gx,   g_x);
    cudaGetSymbolAddress((void**)&gh,   g_h);
    cudaGetSymbolAddress((void**)&gqkv, g_qkv16);
    cudaGetSymbolAddress((void**)&gy,   g_y);
    cudaGetSymbolAddress((void**)&gf1,  g_f1);
    cudaGetSymbolAddress((void**)&wq,   g_wqkv);
    cudaGetSymbolAddress((void**)&wp,   g_wproj);
    cudaGetSymbolAddress((void**)&w1,   g_wf1);
    cudaGetSymbolAddress((void**)&w2,   g_wf2);
    cudaGetSymbolAddress((void**)&wt,   g_wte16);

    cudaFuncSetAttribute(tc_gemm<5, 0, 4>, cudaFuncAttributeMaxDynamicSharedMemorySize, SMEM_MT4);
    cudaFuncSetAttribute(tc_gemm<2, 0, 2>, cudaFuncAttributeMaxDynamicSharedMemorySize, SMEM_MT2);
    cudaFuncSetAttribute(tc_gemm<3, 0, 4>, cudaFuncAttributeMaxDynamicSharedMemorySize, SMEM_MT4);
    cudaFuncSetAttribute(tc_gemm<0, 1, 4>, cudaFuncAttributeMaxDynamicSharedMemorySize, SMEM_MT4);

    // launch order keeps the first qkv GEMM at launch #6 for ncu (-s 5 -c 1)
    embed_kernel<<<(MROW * EMB + 255) / 256, 256>>>(x_idx, wte, wpe, gx);          // 1
    cvtT2_kernel<<<dim3(96, 24, 2 * NLAYER), 256>>>(                               // 2
        attn_w, wq, EMB, 3 * EMB, fc1_w, w1, EMB, 4 * EMB);
    cvtT2_kernel<<<dim3(24, 96, 2 * NLAYER), 256>>>(                               // 3
        proj_w, wp, EMB, EMB, fc2_w, w2, 4 * EMB, EMB);
    cvt_kernel<<<(VOCAB * EMB / 4 + 255) / 256, 256>>>(wte, wt, VOCAB * EMB / 4);  // 4

    for (int l = 0; l < NLAYER; l++) {
        ln_kernel<<<MROW, 256>>>(gx, ln1_w + (size_t)l * EMB, ln1_b + (size_t)l * EMB, gh);  // 5

        // qkv = h @ attn_w + attn_b -> fp16  (N=2304, 128x128 tiles)              // 6 <- ncu
        tc_gemm<5, 0, 4><<<32 * 18, 128, SMEM_MT4>>>(
            gh, wq + (size_t)l * 3 * EMB * EMB,
            attn_b + (size_t)l * 3 * EMB, nullptr, nullptr, gqkv, 3 * EMB, EMB);

        fattn_kernel<<<dim3(BATCH * NHEAD, TLEN / 64), 128>>>(gqkv, gy);

        // x = x + y @ proj_w + proj_b  (N=768, 64x128 tiles -> 384 CTAs)
        tc_gemm<2, 0, 2><<<64 * 6, 128, SMEM_MT2>>>(
            gy, wp + (size_t)l * EMB * EMB,
            proj_b + (size_t)l * EMB, gx, gx, nullptr, EMB, EMB);

        ln_kernel<<<MROW, 256>>>(gx, ln2_w + (size_t)l * EMB, ln2_b + (size_t)l * EMB, gh);

        // f1 = gelu(h @ fc1_w + fc1_b) -> fp16  (N=3072, 128x128 tiles)
        tc_gemm<3, 0, 4><<<32 * 24, 128, SMEM_MT4>>>(
            gh, w1 + (size_t)l * 4 * EMB * EMB,
            fc1_b + (size_t)l * 4 * EMB, nullptr, nullptr, gf1, 4 * EMB, EMB);

        // x = x + f1 @ fc2_w + fc2_b   (N=768, K=3072, 64x128 tiles -> 384 CTAs)
        tc_gemm<2, 0, 2><<<64 * 6, 128, SMEM_MT2>>>(
            gf1, w2 + (size_t)l * 4 * EMB * EMB,
            fc2_b + (size_t)l * EMB, gx, gx, nullptr, EMB, 4 * EMB);
    }

    ln_kernel<<<MROW, 256>>>(gx, lnf_w, lnf_b, gh);

    // logits = h @ wte^T  (N=50257, 128x128 tiles, ragged)
    tc_gemm<0, 1, 4><<<32 * 393, 128, SMEM_MT4>>>(
        gh, wt, nullptr, nullptr, out, nullptr, VOCAB, EMB);
}